// round 3
// baseline (speedup 1.0000x reference)
#include <cuda_runtime.h>
#include <cuda_bf16.h>

// Shapes
#define B_  8
#define S_  96
#define D_  768
#define M_  (B_ * S_ * S_)   // 73728 rows
#define K_  768
#define N1_ 768
#define N2_ 256

// GEMM tiling
#define BM 128
#define BN 64
#define BK 32
#define LDA 40   // padded smem stride (bf16 elems) for A tiles
#define LDW 40   // padded smem stride for transposed W tiles

// ---------------- scratch (static device globals; no allocations) ----------
static __device__ float         g_Y[(size_t)M_ * N1_];        // 226 MB: GEMM1 out / h1
static __device__ __nv_bfloat16 g_Ahi[(size_t)M_ * K_];       // 113 MB
static __device__ __nv_bfloat16 g_Alo[(size_t)M_ * K_];       // 113 MB
static __device__ __nv_bfloat16 g_W1hi[K_ * N1_];
static __device__ __nv_bfloat16 g_W1lo[K_ * N1_];
static __device__ __nv_bfloat16 g_W2hi[K_ * N2_];
static __device__ __nv_bfloat16 g_W2lo[K_ * N2_];

// ---------------- helpers ---------------------------------------------------
__device__ __forceinline__ void fma4(float4& r, float s, const float4 v) {
    r.x += s * v.x; r.y += s * v.y; r.z += s * v.z; r.w += s * v.w;
}

#define MMA_BF16(Cv, Av, Bv) asm volatile( \
    "mma.sync.aligned.m16n8k16.row.col.f32.bf16.bf16.f32 " \
    "{%0,%1,%2,%3}, {%4,%5,%6,%7}, {%8,%9}, {%0,%1,%2,%3};\n" \
    : "+f"((Cv)[0]), "+f"((Cv)[1]), "+f"((Cv)[2]), "+f"((Cv)[3]) \
    : "r"((Av)[0]), "r"((Av)[1]), "r"((Av)[2]), "r"((Av)[3]), \
      "r"((Bv)[0]), "r"((Bv)[1]))

// ---------------- kernel 1: split weights into bf16 hi/lo -------------------
__global__ void conv_w_kernel(const float* __restrict__ W1,
                              const float* __restrict__ W2)
{
    int i = blockIdx.x * blockDim.x + threadIdx.x;
    const int n1 = K_ * N1_;
    const int n2 = K_ * N2_;
    if (i < n1) {
        float w = W1[i];
        __nv_bfloat16 h = __float2bfloat16(w);
        g_W1hi[i] = h;
        g_W1lo[i] = __float2bfloat16(w - __bfloat162float(h));
    } else if (i < n1 + n2) {
        int j = i - n1;
        float w = W2[j];
        __nv_bfloat16 h = __float2bfloat16(w);
        g_W2hi[j] = h;
        g_W2lo[j] = __float2bfloat16(w - __bfloat162float(h));
    }
}

// ---------------- kernel 2: gather stencil + bf16 split ---------------------
// out[b,l,k,d] = 2*h[b,l,k,d] + adj[b,l,k]*h[b,l,l,d]
//              + t[b,k-1]*h[b,l,k-1,d] + t[b,k+1]*h[b,l,k+1,d]
//              + a[b,l-1]*h[b,l-1,k,d] + a[b,l+1]*h[b,l+1,k,d]
// hext == nullptr -> read from g_Y (layer-2 pass). One block per (b,l,k).
__global__ void gather_kernel(const float* __restrict__ hext,
                              const float* __restrict__ a_simi,
                              const float* __restrict__ t_simi,
                              const float* __restrict__ adj)
{
    const float* h = hext ? hext : g_Y;
    const int idx = blockIdx.x;               // (b*S + l)*S + k
    const int k = idx % S_;
    const int l = (idx / S_) % S_;
    const int b = idx / (S_ * S_);
    const int t = threadIdx.x;                // 0..191 (float4 over D=768)

    const float4 cv = ((const float4*)(h + (size_t)idx * D_))[t];
    const float4 dv = ((const float4*)(h + ((size_t)(b * S_ + l) * S_ + l) * D_))[t];
    const float adjv = adj[(size_t)(b * S_ + l) * S_ + k];

    float4 r;
    r.x = 2.f * cv.x + adjv * dv.x;
    r.y = 2.f * cv.y + adjv * dv.y;
    r.z = 2.f * cv.z + adjv * dv.z;
    r.w = 2.f * cv.w + adjv * dv.w;

    if (k > 0) {
        float s = t_simi[b * S_ + k - 1];
        fma4(r, s, ((const float4*)(h + ((size_t)idx - 1) * D_))[t]);
    }
    if (k < S_ - 1) {
        float s = t_simi[b * S_ + k + 1];
        fma4(r, s, ((const float4*)(h + ((size_t)idx + 1) * D_))[t]);
    }
    if (l > 0) {
        float s = a_simi[b * S_ + l - 1];
        fma4(r, s, ((const float4*)(h + ((size_t)idx - S_) * D_))[t]);
    }
    if (l < S_ - 1) {
        float s = a_simi[b * S_ + l + 1];
        fma4(r, s, ((const float4*)(h + ((size_t)idx + S_) * D_))[t]);
    }

    // split into bf16 hi/lo and store (8B vectorized)
    float vals[4] = {r.x, r.y, r.z, r.w};
    __nv_bfloat16 hi[4], lo[4];
#pragma unroll
    for (int j = 0; j < 4; j++) {
        hi[j] = __float2bfloat16(vals[j]);
        lo[j] = __float2bfloat16(vals[j] - __bfloat162float(hi[j]));
    }
    size_t o = (size_t)idx * D_ + t * 4;
    __nv_bfloat162* ph = (__nv_bfloat162*)(g_Ahi + o);
    __nv_bfloat162* pl = (__nv_bfloat162*)(g_Alo + o);
    __nv_bfloat162 v;
    v.x = hi[0]; v.y = hi[1]; ph[0] = v;
    v.x = hi[2]; v.y = hi[3]; ph[1] = v;
    v.x = lo[0]; v.y = lo[1]; pl[0] = v;
    v.x = lo[2]; v.y = lo[3]; pl[1] = v;
}

// ---------------- kernel 3: bf16-split GEMM + bias --------------------------
// C = Ahi@(Whi+Wlo) + Alo@Whi  (+ bias), fp32 accumulate.
// Block 256 thr (8 warps, 4x2), tile 128x64, BK=32. Yext==nullptr -> g_Y.
__global__ void __launch_bounds__(256, 2)
gemm_kernel(int layer, const float* __restrict__ bias, float* __restrict__ Yext, int N)
{
    const __nv_bfloat16* __restrict__ Whi = layer ? g_W2hi : g_W1hi;
    const __nv_bfloat16* __restrict__ Wlo = layer ? g_W2lo : g_W1lo;
    float* Y = Yext ? Yext : g_Y;

    __shared__ __align__(16) __nv_bfloat16 sAhi[BM * LDA];
    __shared__ __align__(16) __nv_bfloat16 sAlo[BM * LDA];
    __shared__ __align__(16) __nv_bfloat16 sWhi[BN * LDW];   // transposed [n][k]
    __shared__ __align__(16) __nv_bfloat16 sWlo[BN * LDW];

    const int tid  = threadIdx.x;
    const int lane = tid & 31;
    const int warp = tid >> 5;
    const int wm = warp >> 1;           // 0..3
    const int wn = warp & 1;            // 0..1
    const int g  = lane >> 2;           // 0..7
    const int tg = lane & 3;            // 0..3

    const int m0 = blockIdx.y * BM;
    const int n0 = blockIdx.x * BN;

    float c[2][4][4];
#pragma unroll
    for (int mi = 0; mi < 2; mi++)
#pragma unroll
        for (int ni = 0; ni < 4; ni++)
#pragma unroll
            for (int j = 0; j < 4; j++) c[mi][ni][j] = 0.f;

    for (int kt = 0; kt < K_; kt += BK) {
        // A tiles: 128x32 bf16 (hi,lo), 4B vectorized, coalesced on k
#pragma unroll
        for (int p = 0; p < 8; p++) {
            int lin = tid + p * 256;           // 0..2047
            int row = lin >> 4;
            int cu  = lin & 15;
            size_t go = (size_t)(m0 + row) * K_ + kt + cu * 2;
            *(unsigned*)(sAhi + row * LDA + cu * 2) = *(const unsigned*)(g_Ahi + go);
            *(unsigned*)(sAlo + row * LDA + cu * 2) = *(const unsigned*)(g_Alo + go);
        }
        // W tiles: 32x64 loaded transposed into [n][k]
#pragma unroll
        for (int p = 0; p < 8; p++) {
            int lin = tid + p * 256;           // 0..2047
            int kr = lin >> 6;                 // 0..31
            int n  = lin & 63;
            size_t wo = (size_t)(kt + kr) * N + n0 + n;
            sWhi[n * LDW + kr] = Whi[wo];
            sWlo[n * LDW + kr] = Wlo[wo];
        }
        __syncthreads();

#pragma unroll
        for (int ks = 0; ks < 2; ks++) {
            const int kb = ks * 16;
            unsigned ahi[2][4], alo[2][4], bhi[4][2], blo[4][2];
#pragma unroll
            for (int mi = 0; mi < 2; mi++) {
                int r = wm * 32 + mi * 16 + g;
                const __nv_bfloat16* pa = sAhi + r * LDA + kb;
                const __nv_bfloat16* pb = sAlo + r * LDA + kb;
                ahi[mi][0] = *(const unsigned*)(pa + 2 * tg);
                ahi[mi][1] = *(const unsigned*)(pa + 8 * LDA + 2 * tg);
                ahi[mi][2] = *(const unsigned*)(pa + 2 * tg + 8);
                ahi[mi][3] = *(const unsigned*)(pa + 8 * LDA + 2 * tg + 8);
                alo[mi][0] = *(const unsigned*)(pb + 2 * tg);
                alo[mi][1] = *(const unsigned*)(pb + 8 * LDA + 2 * tg);
                alo[mi][2] = *(const unsigned*)(pb + 2 * tg + 8);
                alo[mi][3] = *(const unsigned*)(pb + 8 * LDA + 2 * tg + 8);
            }
#pragma unroll
            for (int ni = 0; ni < 4; ni++) {
                int n = wn * 32 + ni * 8 + g;
                const __nv_bfloat16* pw = sWhi + n * LDW + kb;
                const __nv_bfloat16* pl = sWlo + n * LDW + kb;
                bhi[ni][0] = *(const unsigned*)(pw + 2 * tg);
                bhi[ni][1] = *(const unsigned*)(pw + 2 * tg + 8);
                blo[ni][0] = *(const unsigned*)(pl + 2 * tg);
                blo[ni][1] = *(const unsigned*)(pl + 2 * tg + 8);
            }
#pragma unroll
            for (int mi = 0; mi < 2; mi++)
#pragma unroll
                for (int ni = 0; ni < 4; ni++) {
                    MMA_BF16(c[mi][ni], ahi[mi], bhi[ni]);
                    MMA_BF16(c[mi][ni], ahi[mi], blo[ni]);
                    MMA_BF16(c[mi][ni], alo[mi], bhi[ni]);
                }
        }
        __syncthreads();
    }

    // epilogue: + bias, fp32 store
#pragma unroll
    for (int mi = 0; mi < 2; mi++) {
        int r0 = m0 + wm * 32 + mi * 16 + g;
#pragma unroll
        for (int ni = 0; ni < 4; ni++) {
            int col = n0 + wn * 32 + ni * 8 + 2 * tg;
            float2 bv = *(const float2*)(bias + col);
            float2 v0 = make_float2(c[mi][ni][0] + bv.x, c[mi][ni][1] + bv.y);
            float2 v1 = make_float2(c[mi][ni][2] + bv.x, c[mi][ni][3] + bv.y);
            *(float2*)(Y + (size_t)r0 * N + col)       = v0;
            *(float2*)(Y + (size_t)(r0 + 8) * N + col) = v1;
        }
    }
}

// ---------------- kernel 4: T5 RMS-norm + ReLU (in place) -------------------
// One block per row; blockDim = N/4. Yext==nullptr -> g_Y.
__global__ void rms_kernel(float* __restrict__ Yext, const float* __restrict__ gw, int N)
{
    float* Y = Yext ? Yext : g_Y;
    const int row = blockIdx.x;
    const int t = threadIdx.x;
    float4* p = (float4*)(Y + (size_t)row * N);
    const float4 v = p[t];
    float ss = v.x * v.x + v.y * v.y + v.z * v.z + v.w * v.w;
#pragma unroll
    for (int o = 16; o; o >>= 1) ss += __shfl_xor_sync(0xffffffffu, ss, o);
    __shared__ float ws[8];
    if ((t & 31) == 0) ws[t >> 5] = ss;
    __syncthreads();
    float tot = 0.f;
    const int nw = blockDim.x >> 5;
    for (int i = 0; i < nw; i++) tot += ws[i];
    const float r = rsqrtf(tot / (float)N + 1e-12f);
    const float4 g4 = ((const float4*)gw)[t];
    float4 o4;
    o4.x = fmaxf(g4.x * v.x * r, 0.f);
    o4.y = fmaxf(g4.y * v.y * r, 0.f);
    o4.z = fmaxf(g4.z * v.z * r, 0.f);
    o4.w = fmaxf(g4.w * v.w * r, 0.f);
    p[t] = o4;
}

// ---------------- launch ----------------------------------------------------
extern "C" void kernel_launch(void* const* d_in, const int* in_sizes, int n_in,
                              void* d_out, int out_size)
{
    (void)in_sizes; (void)n_in; (void)out_size;
    const float* table  = (const float*)d_in[0];
    const float* a_simi = (const float*)d_in[1];
    const float* t_simi = (const float*)d_in[2];
    const float* adj    = (const float*)d_in[3];
    const float* W1     = (const float*)d_in[4];
    const float* b1     = (const float*)d_in[5];
    const float* g1     = (const float*)d_in[6];
    const float* W2     = (const float*)d_in[7];
    const float* b2     = (const float*)d_in[8];
    const float* g2     = (const float*)d_in[9];
    float* out = (float*)d_out;

    const int nconv = K_ * N1_ + K_ * N2_;
    conv_w_kernel<<<(nconv + 255) / 256, 256>>>(W1, W2);

    // layer 1
    gather_kernel<<<M_, 192>>>(table, a_simi, t_simi, adj);
    gemm_kernel<<<dim3(N1_ / BN, M_ / BM), 256>>>(0, b1, nullptr, N1_);
    rms_kernel<<<M_, N1_ / 4>>>(nullptr, g1, N1_);

    // layer 2
    gather_kernel<<<M_, 192>>>(nullptr, a_simi, t_simi, adj);
    gemm_kernel<<<dim3(N2_ / BN, M_ / BM), 256>>>(1, b2, out, N2_);
    rms_kernel<<<M_, N2_ / 4>>>(out, g2, N2_);
}

// round 5
// speedup vs baseline: 1.2903x; 1.2903x over previous
#include <cuda_runtime.h>
#include <cuda_bf16.h>
#include <cstdint>

// ---------------------------------------------------------------- shapes
#define B_  8
#define S_  96
#define D_  768
#define M_  (B_ * S_ * S_)   // 73728 rows
#define K_  768
#define N1_ 768
#define N2_ 256

// GEMM tiling (mma.sync path, base ISA only)
#define BMg 128
#define BNg 128
#define BKg 32
#define NTg (K_ / BKg)       // 24 k-tiles
#define LDAB 80              // bytes per smem row (32 bf16 = 64B data + 16B pad)
// per-stage smem byte offsets
#define T_AHI 0
#define T_ALO 10240          // 128 rows * 80B
#define T_WHI 20480
#define T_WLO 30720
#define STAGE_BYTES 40960
#define SMEM_G (2 * STAGE_BYTES)   // 81920 B, double buffered

// ---------------- scratch (static device globals; no allocations) ----------
static __device__ float         g_Y[(size_t)M_ * N1_];        // GEMM1 out / h1
static __device__ __nv_bfloat16 g_Ahi[(size_t)M_ * K_];
static __device__ __nv_bfloat16 g_Alo[(size_t)M_ * K_];
static __device__ __nv_bfloat16 g_W1hiT[(size_t)N1_ * K_];    // W^T, k-contiguous
static __device__ __nv_bfloat16 g_W1loT[(size_t)N1_ * K_];
static __device__ __nv_bfloat16 g_W2hiT[(size_t)N2_ * K_];
static __device__ __nv_bfloat16 g_W2loT[(size_t)N2_ * K_];

// ---------------------------------------------------------------- helpers
__device__ __forceinline__ uint32_t smem_u32(const void* p) {
    uint32_t a;
    asm("{ .reg .u64 t; cvta.to.shared.u64 t, %1; cvt.u32.u64 %0, t; }" : "=r"(a) : "l"(p));
    return a;
}

__device__ __forceinline__ void cp16(uint32_t s, const void* g) {
    asm volatile("cp.async.cg.shared.global [%0], [%1], 16;" :: "r"(s), "l"(g));
}
#define CP_COMMIT() asm volatile("cp.async.commit_group;" ::: "memory")
#define CP_WAIT1()  asm volatile("cp.async.wait_group 1;" ::: "memory")
#define CP_WAIT0()  asm volatile("cp.async.wait_group 0;" ::: "memory")

#define LDSM4(r, addr) \
    asm volatile("ldmatrix.sync.aligned.m8n8.x4.shared.b16 {%0,%1,%2,%3}, [%4];" \
        : "=r"((r)[0]), "=r"((r)[1]), "=r"((r)[2]), "=r"((r)[3]) : "r"(addr))

#define MMA_BF16(Cv, Av, Bv) asm volatile( \
    "mma.sync.aligned.m16n8k16.row.col.f32.bf16.bf16.f32 " \
    "{%0,%1,%2,%3}, {%4,%5,%6,%7}, {%8,%9}, {%0,%1,%2,%3};\n" \
    : "+f"((Cv)[0]), "+f"((Cv)[1]), "+f"((Cv)[2]), "+f"((Cv)[3]) \
    : "r"((Av)[0]), "r"((Av)[1]), "r"((Av)[2]), "r"((Av)[3]), \
      "r"((Bv)[0]), "r"((Bv)[1]))

// ---------------- kernel 1: split + transpose weights -----------------------
__global__ void conv_w_kernel(const float* __restrict__ W1,
                              const float* __restrict__ W2)
{
    int i = blockIdx.x * blockDim.x + threadIdx.x;
    const int n1 = K_ * N1_;
    const int n2 = K_ * N2_;
    if (i < n1) {
        int k = i / N1_, n = i % N1_;
        float w = W1[i];
        __nv_bfloat16 h = __float2bfloat16(w);
        g_W1hiT[(size_t)n * K_ + k] = h;
        g_W1loT[(size_t)n * K_ + k] = __float2bfloat16(w - __bfloat162float(h));
    } else if (i < n1 + n2) {
        int j = i - n1;
        int k = j / N2_, n = j % N2_;
        float w = W2[j];
        __nv_bfloat16 h = __float2bfloat16(w);
        g_W2hiT[(size_t)n * K_ + k] = h;
        g_W2loT[(size_t)n * K_ + k] = __float2bfloat16(w - __bfloat162float(h));
    }
}

// ---------------- kernel 2: gather stencil + bf16 split ---------------------
__device__ __forceinline__ void fma4(float4& r, float s, const float4 v) {
    r.x += s * v.x; r.y += s * v.y; r.z += s * v.z; r.w += s * v.w;
}

__global__ void gather_kernel(const float* __restrict__ hext,
                              const float* __restrict__ a_simi,
                              const float* __restrict__ t_simi,
                              const float* __restrict__ adj)
{
    const float* h = hext ? hext : g_Y;
    const int idx = blockIdx.x;               // (b*S + l)*S + k
    const int k = idx % S_;
    const int l = (idx / S_) % S_;
    const int b = idx / (S_ * S_);
    const int t = threadIdx.x;                // 0..191

    const float4 cv = ((const float4*)(h + (size_t)idx * D_))[t];
    const float4 dv = ((const float4*)(h + ((size_t)(b * S_ + l) * S_ + l) * D_))[t];
    const float adjv = adj[(size_t)(b * S_ + l) * S_ + k];

    float4 r;
    r.x = 2.f * cv.x + adjv * dv.x;
    r.y = 2.f * cv.y + adjv * dv.y;
    r.z = 2.f * cv.z + adjv * dv.z;
    r.w = 2.f * cv.w + adjv * dv.w;

    if (k > 0)      fma4(r, t_simi[b * S_ + k - 1], ((const float4*)(h + ((size_t)idx - 1) * D_))[t]);
    if (k < S_ - 1) fma4(r, t_simi[b * S_ + k + 1], ((const float4*)(h + ((size_t)idx + 1) * D_))[t]);
    if (l > 0)      fma4(r, a_simi[b * S_ + l - 1], ((const float4*)(h + ((size_t)idx - S_) * D_))[t]);
    if (l < S_ - 1) fma4(r, a_simi[b * S_ + l + 1], ((const float4*)(h + ((size_t)idx + S_) * D_))[t]);

    float vals[4] = {r.x, r.y, r.z, r.w};
    __nv_bfloat16 hi[4], lo[4];
#pragma unroll
    for (int j = 0; j < 4; j++) {
        hi[j] = __float2bfloat16(vals[j]);
        lo[j] = __float2bfloat16(vals[j] - __bfloat162float(hi[j]));
    }
    size_t o = (size_t)idx * D_ + t * 4;
    __nv_bfloat162* ph = (__nv_bfloat162*)(g_Ahi + o);
    __nv_bfloat162* pl = (__nv_bfloat162*)(g_Alo + o);
    __nv_bfloat162 v;
    v.x = hi[0]; v.y = hi[1]; ph[0] = v;
    v.x = hi[2]; v.y = hi[3]; ph[1] = v;
    v.x = lo[0]; v.y = lo[1]; pl[0] = v;
    v.x = lo[2]; v.y = lo[3]; pl[1] = v;
}

// ---------------- kernel 3: mma.sync bf16-split GEMM + bias -----------------
// C = Ahi@Whi^T + Ahi@Wlo^T + Alo@Whi^T + bias.
// CTA tile 128x128x32, 512 thr (4x4 warps, 32x32/warp), cp.async double buffer,
// ldmatrix.x4 fragment loads. Smem rows padded to 80B -> conflict-free LDSM.
__global__ void __launch_bounds__(512, 1)
gemm_mma_kernel(int layer, const float* __restrict__ bias,
                float* __restrict__ Yext, int N)
{
    extern __shared__ __align__(128) char smem[];
    const __nv_bfloat16* __restrict__ WhT = layer ? g_W2hiT : g_W1hiT;
    const __nv_bfloat16* __restrict__ WlT = layer ? g_W2loT : g_W1loT;
    float* Y = Yext ? Yext : g_Y;

    const int tid  = threadIdx.x;
    const int wid  = tid >> 5;
    const int lane = tid & 31;
    const int wm   = wid & 3;           // warp m index (0..3)
    const int wn   = wid >> 2;          // warp n index (0..3)
    const int m0 = blockIdx.y * BMg;
    const int n0 = blockIdx.x * BNg;
    const uint32_t sb = smem_u32(smem);

    // cp.async mapping: 512 threads, each copies one 16B chunk per tensor.
    const int lrow = tid >> 2;          // 0..127
    const int lch  = tid & 3;           // 0..3 (16B chunks across 64B row)
    const uint32_t sOff = (uint32_t)(lrow * LDAB + lch * 16);
    const size_t gA = (size_t)(m0 + lrow) * K_ + lch * 8;
    const size_t gW = (size_t)(n0 + lrow) * K_ + lch * 8;

    float c[2][4][4] = {};

    // prologue: stage 0
    {
        uint32_t s = sb + sOff;
        cp16(s + T_AHI, g_Ahi + gA);
        cp16(s + T_ALO, g_Alo + gA);
        cp16(s + T_WHI, WhT + gW);
        cp16(s + T_WLO, WlT + gW);
        CP_COMMIT();
    }

    for (int t = 0; t < NTg; t++) {
        if (t + 1 < NTg) {
            uint32_t s = sb + (uint32_t)((t + 1) & 1) * STAGE_BYTES + sOff;
            const int kt = (t + 1) * BKg;
            cp16(s + T_AHI, g_Ahi + gA + kt);
            cp16(s + T_ALO, g_Alo + gA + kt);
            cp16(s + T_WHI, WhT + gW + kt);
            cp16(s + T_WLO, WlT + gW + kt);
            CP_COMMIT();
            CP_WAIT1();          // oldest group (stage t) complete
        } else {
            CP_WAIT0();
        }
        __syncthreads();

        const uint32_t bufb = sb + (uint32_t)(t & 1) * STAGE_BYTES;
#pragma unroll
        for (int ks = 0; ks < 2; ks++) {
            const uint32_t kb = (uint32_t)(ks * 32 + (lane >> 4) * 16);
            uint32_t ah[2][4], al[2][4], bh[2][4], bl[2][4];
#pragma unroll
            for (int mi = 0; mi < 2; mi++) {
                uint32_t r = (uint32_t)((wm * 32 + mi * 16 + (lane & 15)) * LDAB) + kb;
                LDSM4(ah[mi], bufb + T_AHI + r);
                LDSM4(al[mi], bufb + T_ALO + r);
            }
#pragma unroll
            for (int nj = 0; nj < 2; nj++) {
                uint32_t r = (uint32_t)((wn * 32 + nj * 16 + (lane & 15)) * LDAB) + kb;
                LDSM4(bh[nj], bufb + T_WHI + r);
                LDSM4(bl[nj], bufb + T_WLO + r);
            }
#pragma unroll
            for (int mi = 0; mi < 2; mi++)
#pragma unroll
                for (int nj = 0; nj < 2; nj++) {
                    uint32_t fh0[2] = {bh[nj][0], bh[nj][2]};  // first n8 of n16 tile
                    uint32_t fh1[2] = {bh[nj][1], bh[nj][3]};  // second n8
                    uint32_t fl0[2] = {bl[nj][0], bl[nj][2]};
                    uint32_t fl1[2] = {bl[nj][1], bl[nj][3]};
                    MMA_BF16(c[mi][2 * nj],     ah[mi], fh0);
                    MMA_BF16(c[mi][2 * nj],     al[mi], fh0);
                    MMA_BF16(c[mi][2 * nj],     ah[mi], fl0);
                    MMA_BF16(c[mi][2 * nj + 1], ah[mi], fh1);
                    MMA_BF16(c[mi][2 * nj + 1], al[mi], fh1);
                    MMA_BF16(c[mi][2 * nj + 1], ah[mi], fl1);
                }
        }
        __syncthreads();
    }

    // epilogue: + bias, fp32 store
#pragma unroll
    for (int mi = 0; mi < 2; mi++) {
        const int row = m0 + wm * 32 + mi * 16 + (lane >> 2);
#pragma unroll
        for (int ni = 0; ni < 4; ni++) {
            const int col = n0 + wn * 32 + ni * 8 + 2 * (lane & 3);
            float2 bv = *(const float2*)(bias + col);
            float2 v0 = make_float2(c[mi][ni][0] + bv.x, c[mi][ni][1] + bv.y);
            float2 v1 = make_float2(c[mi][ni][2] + bv.x, c[mi][ni][3] + bv.y);
            *(float2*)(Y + (size_t)row * N + col)       = v0;
            *(float2*)(Y + (size_t)(row + 8) * N + col) = v1;
        }
    }
}

// ---------------- kernel 4: T5 RMS-norm + ReLU (in place) -------------------
__global__ void rms_kernel(float* __restrict__ Yext, const float* __restrict__ gw, int N)
{
    float* Y = Yext ? Yext : g_Y;
    const int row = blockIdx.x;
    const int t = threadIdx.x;
    float4* p = (float4*)(Y + (size_t)row * N);
    const float4 v = p[t];
    float ss = v.x * v.x + v.y * v.y + v.z * v.z + v.w * v.w;
#pragma unroll
    for (int o = 16; o; o >>= 1) ss += __shfl_xor_sync(0xffffffffu, ss, o);
    __shared__ float ws[8];
    if ((t & 31) == 0) ws[t >> 5] = ss;
    __syncthreads();
    float tot = 0.f;
    const int nw = blockDim.x >> 5;
    for (int i = 0; i < nw; i++) tot += ws[i];
    const float r = rsqrtf(tot / (float)N + 1e-12f);
    const float4 g4 = ((const float4*)gw)[t];
    float4 o4;
    o4.x = fmaxf(g4.x * v.x * r, 0.f);
    o4.y = fmaxf(g4.y * v.y * r, 0.f);
    o4.z = fmaxf(g4.z * v.z * r, 0.f);
    o4.w = fmaxf(g4.w * v.w * r, 0.f);
    p[t] = o4;
}

// ---------------- launch ----------------------------------------------------
extern "C" void kernel_launch(void* const* d_in, const int* in_sizes, int n_in,
                              void* d_out, int out_size)
{
    (void)in_sizes; (void)n_in; (void)out_size;
    const float* table  = (const float*)d_in[0];
    const float* a_simi = (const float*)d_in[1];
    const float* t_simi = (const float*)d_in[2];
    const float* adj    = (const float*)d_in[3];
    const float* W1     = (const float*)d_in[4];
    const float* b1     = (const float*)d_in[5];
    const float* g1     = (const float*)d_in[6];
    const float* W2     = (const float*)d_in[7];
    const float* b2     = (const float*)d_in[8];
    const float* g2     = (const float*)d_in[9];
    float* out = (float*)d_out;

    static bool attr_set = false;
    if (!attr_set) {
        // executed on the (uncaptured) correctness call; skipped during capture
        cudaFuncSetAttribute(gemm_mma_kernel,
                             cudaFuncAttributeMaxDynamicSharedMemorySize, SMEM_G);
        attr_set = true;
    }

    const int nconv = K_ * (N1_ + N2_);
    conv_w_kernel<<<(nconv + 255) / 256, 256>>>(W1, W2);

    // layer 1
    gather_kernel<<<M_, 192>>>(table, a_simi, t_simi, adj);
    gemm_mma_kernel<<<dim3(N1_ / BNg, M_ / BMg), 512, SMEM_G>>>(0, b1, nullptr, N1_);
    rms_kernel<<<M_, N1_ / 4>>>(nullptr, g1, N1_);

    // layer 2
    gather_kernel<<<M_, 192>>>(nullptr, a_simi, t_simi, adj);
    gemm_mma_kernel<<<dim3(N2_ / BNg, M_ / BMg), 512, SMEM_G>>>(1, b2, out, N2_);
    rms_kernel<<<M_, N2_ / 4>>>(out, g2, N2_);
}

// round 6
// speedup vs baseline: 1.3376x; 1.0367x over previous
#include <cuda_runtime.h>
#include <cuda_bf16.h>
#include <cstdint>

// ---------------------------------------------------------------- shapes
#define B_  8
#define S_  96
#define D_  768
#define M_  (B_ * S_ * S_)   // 73728 rows
#define K_  768
#define N1_ 768
#define N2_ 256

// GEMM tiling (mma.sync path, base ISA only)
#define BMg 256              // CTA M
#define BNg 128              // CTA N
#define BKg 32               // k per stage
#define NTg (K_ / BKg)       // 24 k-tiles
#define LDAB 80              // bytes per smem row (32 bf16 = 64B data + 16B pad)
// per-stage smem byte offsets
#define T_AHI 0
#define T_ALO 20480          // 256 rows * 80B
#define T_WHI 40960
#define T_WLO 51200          // 128 rows * 80B
#define STAGE_BYTES 61440
#define NSTAGE 3
#define SMEM_G (NSTAGE * STAGE_BYTES)   // 184320 B

// ---------------- scratch (static device globals; no allocations) ----------
static __device__ float         g_Y[(size_t)M_ * N1_];        // GEMM1 out / h1
static __device__ __nv_bfloat16 g_Ahi[(size_t)M_ * K_];
static __device__ __nv_bfloat16 g_Alo[(size_t)M_ * K_];
static __device__ __nv_bfloat16 g_W1hiT[(size_t)N1_ * K_];    // W^T, k-contiguous
static __device__ __nv_bfloat16 g_W1loT[(size_t)N1_ * K_];
static __device__ __nv_bfloat16 g_W2hiT[(size_t)N2_ * K_];
static __device__ __nv_bfloat16 g_W2loT[(size_t)N2_ * K_];

// ---------------------------------------------------------------- helpers
__device__ __forceinline__ uint32_t smem_u32(const void* p) {
    uint32_t a;
    asm("{ .reg .u64 t; cvta.to.shared.u64 t, %1; cvt.u32.u64 %0, t; }" : "=r"(a) : "l"(p));
    return a;
}

__device__ __forceinline__ void cp16(uint32_t s, const void* g) {
    asm volatile("cp.async.cg.shared.global [%0], [%1], 16;" :: "r"(s), "l"(g));
}
#define CP_COMMIT() asm volatile("cp.async.commit_group;" ::: "memory")
#define CP_WAIT1()  asm volatile("cp.async.wait_group 1;" ::: "memory")
#define CP_WAIT0()  asm volatile("cp.async.wait_group 0;" ::: "memory")

#define LDSM4(r, addr) \
    asm volatile("ldmatrix.sync.aligned.m8n8.x4.shared.b16 {%0,%1,%2,%3}, [%4];" \
        : "=r"((r)[0]), "=r"((r)[1]), "=r"((r)[2]), "=r"((r)[3]) : "r"(addr))

#define MMA_BF16(Cv, Av, Bv) asm volatile( \
    "mma.sync.aligned.m16n8k16.row.col.f32.bf16.bf16.f32 " \
    "{%0,%1,%2,%3}, {%4,%5,%6,%7}, {%8,%9}, {%0,%1,%2,%3};\n" \
    : "+f"((Cv)[0]), "+f"((Cv)[1]), "+f"((Cv)[2]), "+f"((Cv)[3]) \
    : "r"((Av)[0]), "r"((Av)[1]), "r"((Av)[2]), "r"((Av)[3]), \
      "r"((Bv)[0]), "r"((Bv)[1]))

// ---------------- kernel 1: split + transpose weights -----------------------
__global__ void conv_w_kernel(const float* __restrict__ W1,
                              const float* __restrict__ W2)
{
    int i = blockIdx.x * blockDim.x + threadIdx.x;
    const int n1 = K_ * N1_;
    const int n2 = K_ * N2_;
    if (i < n1) {
        int k = i / N1_, n = i % N1_;
        float w = W1[i];
        __nv_bfloat16 h = __float2bfloat16(w);
        g_W1hiT[(size_t)n * K_ + k] = h;
        g_W1loT[(size_t)n * K_ + k] = __float2bfloat16(w - __bfloat162float(h));
    } else if (i < n1 + n2) {
        int j = i - n1;
        int k = j / N2_, n = j % N2_;
        float w = W2[j];
        __nv_bfloat16 h = __float2bfloat16(w);
        g_W2hiT[(size_t)n * K_ + k] = h;
        g_W2loT[(size_t)n * K_ + k] = __float2bfloat16(w - __bfloat162float(h));
    }
}

// ---------------- kernel 2: gather stencil + bf16 split ---------------------
__device__ __forceinline__ void fma4(float4& r, float s, const float4 v) {
    r.x += s * v.x; r.y += s * v.y; r.z += s * v.z; r.w += s * v.w;
}

__global__ void gather_kernel(const float* __restrict__ hext,
                              const float* __restrict__ a_simi,
                              const float* __restrict__ t_simi,
                              const float* __restrict__ adj)
{
    const float* h = hext ? hext : g_Y;
    const int idx = blockIdx.x;               // (b*S + l)*S + k
    const int k = idx % S_;
    const int l = (idx / S_) % S_;
    const int b = idx / (S_ * S_);
    const int t = threadIdx.x;                // 0..191

    const float4 cv = ((const float4*)(h + (size_t)idx * D_))[t];
    const float4 dv = ((const float4*)(h + ((size_t)(b * S_ + l) * S_ + l) * D_))[t];
    const float adjv = adj[(size_t)(b * S_ + l) * S_ + k];

    float4 r;
    r.x = 2.f * cv.x + adjv * dv.x;
    r.y = 2.f * cv.y + adjv * dv.y;
    r.z = 2.f * cv.z + adjv * dv.z;
    r.w = 2.f * cv.w + adjv * dv.w;

    if (k > 0)      fma4(r, t_simi[b * S_ + k - 1], ((const float4*)(h + ((size_t)idx - 1) * D_))[t]);
    if (k < S_ - 1) fma4(r, t_simi[b * S_ + k + 1], ((const float4*)(h + ((size_t)idx + 1) * D_))[t]);
    if (l > 0)      fma4(r, a_simi[b * S_ + l - 1], ((const float4*)(h + ((size_t)idx - S_) * D_))[t]);
    if (l < S_ - 1) fma4(r, a_simi[b * S_ + l + 1], ((const float4*)(h + ((size_t)idx + S_) * D_))[t]);

    float vals[4] = {r.x, r.y, r.z, r.w};
    __nv_bfloat16 hi[4], lo[4];
#pragma unroll
    for (int j = 0; j < 4; j++) {
        hi[j] = __float2bfloat16(vals[j]);
        lo[j] = __float2bfloat16(vals[j] - __bfloat162float(hi[j]));
    }
    size_t o = (size_t)idx * D_ + t * 4;
    __nv_bfloat162* ph = (__nv_bfloat162*)(g_Ahi + o);
    __nv_bfloat162* pl = (__nv_bfloat162*)(g_Alo + o);
    __nv_bfloat162 v;
    v.x = hi[0]; v.y = hi[1]; ph[0] = v;
    v.x = hi[2]; v.y = hi[3]; ph[1] = v;
    v.x = lo[0]; v.y = lo[1]; pl[0] = v;
    v.x = lo[2]; v.y = lo[3]; pl[1] = v;
}

// ---------------- kernel 3: mma.sync bf16-split GEMM + bias -----------------
// C = Ahi@Whi^T + Ahi@Wlo^T + Alo@Whi^T + bias.
// CTA tile 256x128x32, 256 thr (8 warps as 4Mx2N, warp tile 64x64),
// 3-stage cp.async pipeline, ldmatrix.x4 fragment loads, 80B-padded rows.
__global__ void __launch_bounds__(256, 1)
gemm_mma_kernel(int layer, const float* __restrict__ bias,
                float* __restrict__ Yext, int N)
{
    extern __shared__ __align__(128) char smem[];
    const __nv_bfloat16* __restrict__ WhT = layer ? g_W2hiT : g_W1hiT;
    const __nv_bfloat16* __restrict__ WlT = layer ? g_W2loT : g_W1loT;
    float* Y = Yext ? Yext : g_Y;

    const int tid  = threadIdx.x;
    const int wid  = tid >> 5;
    const int lane = tid & 31;
    const int wm   = wid & 3;            // warp m index (0..3), 64 rows each
    const int wn   = wid >> 2;           // warp n index (0..1), 64 cols each
    const int m0 = blockIdx.y * BMg;
    const int n0 = blockIdx.x * BNg;
    const uint32_t sb = smem_u32(smem);

    // cp.async mapping: thread handles rows {tid>>2 (+64,+128,+192)}, chunk tid&3
    const int lrow = tid >> 2;           // 0..63
    const int lch  = tid & 3;            // 16B chunk in 64B k-row
    const uint32_t sRow = (uint32_t)(lrow * LDAB + lch * 16);

    float c[4][8][4] = {};

#define LOAD_STAGE(st, kt_) do {                                               \
        uint32_t s = sb + (uint32_t)(st) * STAGE_BYTES + sRow;                 \
        _Pragma("unroll")                                                      \
        for (int i_ = 0; i_ < 4; i_++) {                                       \
            size_t gA_ = (size_t)(m0 + lrow + i_ * 64) * K_ + (kt_) + lch * 8; \
            cp16(s + T_AHI + (uint32_t)(i_ * 64 * LDAB), g_Ahi + gA_);         \
            cp16(s + T_ALO + (uint32_t)(i_ * 64 * LDAB), g_Alo + gA_);         \
        }                                                                      \
        _Pragma("unroll")                                                      \
        for (int i_ = 0; i_ < 2; i_++) {                                       \
            size_t gW_ = (size_t)(n0 + lrow + i_ * 64) * K_ + (kt_) + lch * 8; \
            cp16(s + T_WHI + (uint32_t)(i_ * 64 * LDAB), WhT + gW_);           \
            cp16(s + T_WLO + (uint32_t)(i_ * 64 * LDAB), WlT + gW_);           \
        }                                                                      \
        CP_COMMIT();                                                           \
    } while (0)

    LOAD_STAGE(0, 0);
    LOAD_STAGE(1, BKg);

    for (int t = 0; t < NTg; t++) {
        if (t < NTg - 1) CP_WAIT1(); else CP_WAIT0();
        __syncthreads();
        if (t + 2 < NTg) LOAD_STAGE((t + 2) % NSTAGE, (t + 2) * BKg);

        const uint32_t bufb = sb + (uint32_t)(t % NSTAGE) * STAGE_BYTES;
#pragma unroll
        for (int ks = 0; ks < 2; ks++) {
            const uint32_t kb = (uint32_t)(ks * 32 + (lane >> 4) * 16);
            uint32_t ah[4][4], al[4][4], bh[4][4], bl[4][4];
#pragma unroll
            for (int mi = 0; mi < 4; mi++) {
                uint32_t r = (uint32_t)((wm * 64 + mi * 16 + (lane & 15)) * LDAB) + kb;
                LDSM4(ah[mi], bufb + T_AHI + r);
                LDSM4(al[mi], bufb + T_ALO + r);
            }
#pragma unroll
            for (int nj = 0; nj < 4; nj++) {
                uint32_t r = (uint32_t)((wn * 64 + nj * 16 + (lane & 15)) * LDAB) + kb;
                LDSM4(bh[nj], bufb + T_WHI + r);
                LDSM4(bl[nj], bufb + T_WLO + r);
            }
#pragma unroll
            for (int mi = 0; mi < 4; mi++)
#pragma unroll
                for (int nj = 0; nj < 4; nj++) {
                    uint32_t fh0[2] = {bh[nj][0], bh[nj][2]};
                    uint32_t fh1[2] = {bh[nj][1], bh[nj][3]};
                    uint32_t fl0[2] = {bl[nj][0], bl[nj][2]};
                    uint32_t fl1[2] = {bl[nj][1], bl[nj][3]};
                    MMA_BF16(c[mi][2 * nj],     ah[mi], fh0);
                    MMA_BF16(c[mi][2 * nj],     al[mi], fh0);
                    MMA_BF16(c[mi][2 * nj],     ah[mi], fl0);
                    MMA_BF16(c[mi][2 * nj + 1], ah[mi], fh1);
                    MMA_BF16(c[mi][2 * nj + 1], al[mi], fh1);
                    MMA_BF16(c[mi][2 * nj + 1], ah[mi], fl1);
                }
        }
        __syncthreads();
    }
#undef LOAD_STAGE

    // epilogue: + bias, fp32 store
#pragma unroll
    for (int mi = 0; mi < 4; mi++) {
        const int row = m0 + wm * 64 + mi * 16 + (lane >> 2);
#pragma unroll
        for (int ni = 0; ni < 8; ni++) {
            const int col = n0 + wn * 64 + ni * 8 + 2 * (lane & 3);
            float2 bv = *(const float2*)(bias + col);
            float2 v0 = make_float2(c[mi][ni][0] + bv.x, c[mi][ni][1] + bv.y);
            float2 v1 = make_float2(c[mi][ni][2] + bv.x, c[mi][ni][3] + bv.y);
            *(float2*)(Y + (size_t)row * N + col)       = v0;
            *(float2*)(Y + (size_t)(row + 8) * N + col) = v1;
        }
    }
}

// ---------------- kernel 4: T5 RMS-norm + ReLU (in place) -------------------
__global__ void rms_kernel(float* __restrict__ Yext, const float* __restrict__ gw, int N)
{
    float* Y = Yext ? Yext : g_Y;
    const int row = blockIdx.x;
    const int t = threadIdx.x;
    float4* p = (float4*)(Y + (size_t)row * N);
    const float4 v = p[t];
    float ss = v.x * v.x + v.y * v.y + v.z * v.z + v.w * v.w;
#pragma unroll
    for (int o = 16; o; o >>= 1) ss += __shfl_xor_sync(0xffffffffu, ss, o);
    __shared__ float ws[8];
    if ((t & 31) == 0) ws[t >> 5] = ss;
    __syncthreads();
    float tot = 0.f;
    const int nw = blockDim.x >> 5;
    for (int i = 0; i < nw; i++) tot += ws[i];
    const float r = rsqrtf(tot / (float)N + 1e-12f);
    const float4 g4 = ((const float4*)gw)[t];
    float4 o4;
    o4.x = fmaxf(g4.x * v.x * r, 0.f);
    o4.y = fmaxf(g4.y * v.y * r, 0.f);
    o4.z = fmaxf(g4.z * v.z * r, 0.f);
    o4.w = fmaxf(g4.w * v.w * r, 0.f);
    p[t] = o4;
}

// ---------------- launch ----------------------------------------------------
extern "C" void kernel_launch(void* const* d_in, const int* in_sizes, int n_in,
                              void* d_out, int out_size)
{
    (void)in_sizes; (void)n_in; (void)out_size;
    const float* table  = (const float*)d_in[0];
    const float* a_simi = (const float*)d_in[1];
    const float* t_simi = (const float*)d_in[2];
    const float* adj    = (const float*)d_in[3];
    const float* W1     = (const float*)d_in[4];
    const float* b1     = (const float*)d_in[5];
    const float* g1     = (const float*)d_in[6];
    const float* W2     = (const float*)d_in[7];
    const float* b2     = (const float*)d_in[8];
    const float* g2     = (const float*)d_in[9];
    float* out = (float*)d_out;

    static bool attr_set = false;
    if (!attr_set) {
        // executed on the (uncaptured) correctness call; skipped during capture
        cudaFuncSetAttribute(gemm_mma_kernel,
                             cudaFuncAttributeMaxDynamicSharedMemorySize, SMEM_G);
        attr_set = true;
    }

    const int nconv = K_ * (N1_ + N2_);
    conv_w_kernel<<<(nconv + 255) / 256, 256>>>(W1, W2);

    // layer 1
    gather_kernel<<<M_, 192>>>(table, a_simi, t_simi, adj);
    gemm_mma_kernel<<<dim3(N1_ / BNg, M_ / BMg), 256, SMEM_G>>>(0, b1, nullptr, N1_);
    rms_kernel<<<M_, N1_ / 4>>>(nullptr, g1, N1_);

    // layer 2
    gather_kernel<<<M_, 192>>>(nullptr, a_simi, t_simi, adj);
    gemm_mma_kernel<<<dim3(N2_ / BNg, M_ / BMg), 256, SMEM_G>>>(1, b2, out, N2_);
    rms_kernel<<<M_, N2_ / 4>>>(out, g2, N2_);
}

// round 8
// speedup vs baseline: 1.8232x; 1.3630x over previous
#include <cuda_runtime.h>
#include <cuda_fp16.h>
#include <cstdint>

// ---------------------------------------------------------------- shapes
#define B_  8
#define S_  96
#define D_  768
#define M_  (B_ * S_ * S_)   // 73728 rows
#define K_  768
#define N1_ 768
#define N2_ 256

// GEMM tiling (mma.sync path, base ISA only)
#define BMg 256              // CTA M
#define BNg 128              // CTA N
#define BKg 32               // k per stage
#define NTg (K_ / BKg)       // 24 k-tiles
#define LDAB 80              // bytes per smem row (32 fp16 = 64B data + 16B pad)
// per-stage smem byte offsets
#define T_AHI 0
#define T_ALO 20480          // 256 rows * 80B
#define T_W   40960          // 128 rows * 80B
#define STAGE_BYTES 51200
#define NSTAGE 3
#define SMEM_G (NSTAGE * STAGE_BYTES)   // 153600 B

// ---------------- scratch (static device globals; no allocations) ----------
static __device__ float  g_Y[(size_t)M_ * N1_];        // GEMM1 out (pre-norm)
static __device__ float  g_rsum[M_];                   // per-row sum of squares
static __device__ float  g_rfac[M_];                   // rsqrt factors
static __device__ __half g_Ahi[(size_t)M_ * K_];
static __device__ __half g_Alo[(size_t)M_ * K_];
static __device__ __half g_W1T[(size_t)N1_ * K_];      // W^T, k-contiguous, fp16
static __device__ __half g_W2T[(size_t)N2_ * K_];

// ---------------------------------------------------------------- helpers
__device__ __forceinline__ uint32_t smem_u32(const void* p) {
    uint32_t a;
    asm("{ .reg .u64 t; cvta.to.shared.u64 t, %1; cvt.u32.u64 %0, t; }" : "=r"(a) : "l"(p));
    return a;
}

__device__ __forceinline__ void cp16(uint32_t s, const void* g) {
    asm volatile("cp.async.cg.shared.global [%0], [%1], 16;" :: "r"(s), "l"(g));
}
#define CP_COMMIT() asm volatile("cp.async.commit_group;" ::: "memory")
#define CP_WAIT1()  asm volatile("cp.async.wait_group 1;" ::: "memory")
#define CP_WAIT0()  asm volatile("cp.async.wait_group 0;" ::: "memory")

#define LDSM4(r, addr) \
    asm volatile("ldmatrix.sync.aligned.m8n8.x4.shared.b16 {%0,%1,%2,%3}, [%4];" \
        : "=r"((r)[0]), "=r"((r)[1]), "=r"((r)[2]), "=r"((r)[3]) : "r"(addr))

#define MMA_F16(Cv, Av, Bv) asm volatile( \
    "mma.sync.aligned.m16n8k16.row.col.f32.f16.f16.f32 " \
    "{%0,%1,%2,%3}, {%4,%5,%6,%7}, {%8,%9}, {%0,%1,%2,%3};\n" \
    : "+f"((Cv)[0]), "+f"((Cv)[1]), "+f"((Cv)[2]), "+f"((Cv)[3]) \
    : "r"((Av)[0]), "r"((Av)[1]), "r"((Av)[2]), "r"((Av)[3]), \
      "r"((Bv)[0]), "r"((Bv)[1]))

// ---------------- kernel 1: fp16 + transpose weights, zero rsum -------------
__global__ void conv_w_kernel(const float* __restrict__ W1,
                              const float* __restrict__ W2)
{
    int i = blockIdx.x * blockDim.x + threadIdx.x;
    const int n1 = K_ * N1_;
    const int n2 = K_ * N2_;
    if (i < M_) g_rsum[i] = 0.f;
    if (i < n1) {
        int k = i / N1_, n = i % N1_;
        g_W1T[(size_t)n * K_ + k] = __float2half(W1[i]);
    } else if (i < n1 + n2) {
        int j = i - n1;
        int k = j / N2_, n = j % N2_;
        g_W2T[(size_t)n * K_ + k] = __float2half(W2[j]);
    }
}

// ---------------- kernel 2: gather stencil (+opt norm) + fp16 split ---------
__device__ __forceinline__ void fma4(float4& r, float s, const float4 v) {
    r.x += s * v.x; r.y += s * v.y; r.z += s * v.z; r.w += s * v.w;
}

// load one float4 from row `src`; if use_norm, apply relu(g * x * g_rfac[src]).
// g_rfac referenced from DEVICE code (valid address), never passed from host.
__device__ __forceinline__ float4 load4(const float* __restrict__ h, int src, int t,
                                        int use_norm, const float4 g4)
{
    float4 v = ((const float4*)(h + (size_t)src * D_))[t];
    if (use_norm) {
        const float r = g_rfac[src];
        v.x = fmaxf(g4.x * v.x * r, 0.f);
        v.y = fmaxf(g4.y * v.y * r, 0.f);
        v.z = fmaxf(g4.z * v.z * r, 0.f);
        v.w = fmaxf(g4.w * v.w * r, 0.f);
    }
    return v;
}

__global__ void gather_kernel(const float* __restrict__ hext,
                              const float* __restrict__ a_simi,
                              const float* __restrict__ t_simi,
                              const float* __restrict__ adj,
                              int use_norm,
                              const float* __restrict__ gw)
{
    const float* h = hext ? hext : g_Y;
    const int idx = blockIdx.x;               // (b*S + l)*S + k
    const int k = idx % S_;
    const int l = (idx / S_) % S_;
    const int b = idx / (S_ * S_);
    const int t = threadIdx.x;                // 0..191

    float4 g4 = make_float4(1.f, 1.f, 1.f, 1.f);
    if (use_norm) g4 = ((const float4*)gw)[t];

    const float4 cv = load4(h, idx, t, use_norm, g4);
    const float4 dv = load4(h, (b * S_ + l) * S_ + l, t, use_norm, g4);
    const float adjv = adj[(size_t)(b * S_ + l) * S_ + k];

    float4 r;
    r.x = 2.f * cv.x + adjv * dv.x;
    r.y = 2.f * cv.y + adjv * dv.y;
    r.z = 2.f * cv.z + adjv * dv.z;
    r.w = 2.f * cv.w + adjv * dv.w;

    if (k > 0)      fma4(r, t_simi[b * S_ + k - 1], load4(h, idx - 1,  t, use_norm, g4));
    if (k < S_ - 1) fma4(r, t_simi[b * S_ + k + 1], load4(h, idx + 1,  t, use_norm, g4));
    if (l > 0)      fma4(r, a_simi[b * S_ + l - 1], load4(h, idx - S_, t, use_norm, g4));
    if (l < S_ - 1) fma4(r, a_simi[b * S_ + l + 1], load4(h, idx + S_, t, use_norm, g4));

    float vals[4] = {r.x, r.y, r.z, r.w};
    __half hi[4], lo[4];
#pragma unroll
    for (int j = 0; j < 4; j++) {
        hi[j] = __float2half(vals[j]);
        lo[j] = __float2half(vals[j] - __half2float(hi[j]));
    }
    size_t o = (size_t)idx * D_ + t * 4;
    __half2* ph = (__half2*)(g_Ahi + o);
    __half2* pl = (__half2*)(g_Alo + o);
    __half2 v;
    v.x = hi[0]; v.y = hi[1]; ph[0] = v;
    v.x = hi[2]; v.y = hi[3]; ph[1] = v;
    v.x = lo[0]; v.y = lo[1]; pl[0] = v;
    v.x = lo[2]; v.y = lo[3]; pl[1] = v;
}

// ---------------- kernel 3: rfac = rsqrt(rsum/D + eps) ----------------------
__global__ void rfac_kernel()
{
    int i = blockIdx.x * blockDim.x + threadIdx.x;
    if (i < M_) g_rfac[i] = rsqrtf(g_rsum[i] * (1.f / (float)N1_) + 1e-12f);
}

// ---------------- kernel 4: mma.sync fp16 2-product GEMM + bias -------------
// C = Ahi@W^T + Alo@W^T + bias; optional per-row sum-of-squares accumulation.
// CTA tile 256x128x32, 256 thr (8 warps 4Mx2N, warp tile 64x64),
// 3-stage cp.async pipeline, ldmatrix.x4, 80B-padded rows.
__global__ void __launch_bounds__(256, 1)
gemm_mma_kernel(int layer, const float* __restrict__ bias,
                float* __restrict__ Yext, int N, int do_rsum)
{
    extern __shared__ __align__(128) char smem[];
    const __half* __restrict__ WT = layer ? g_W2T : g_W1T;
    float* Y = Yext ? Yext : g_Y;

    const int tid  = threadIdx.x;
    const int wid  = tid >> 5;
    const int lane = tid & 31;
    const int wm   = wid & 3;            // warp m index (0..3), 64 rows each
    const int wn   = wid >> 2;           // warp n index (0..1), 64 cols each
    const int m0 = blockIdx.y * BMg;
    const int n0 = blockIdx.x * BNg;
    const uint32_t sb = smem_u32(smem);

    const int lrow = tid >> 2;           // 0..63
    const int lch  = tid & 3;            // 16B chunk in 64B k-row
    const uint32_t sRow = (uint32_t)(lrow * LDAB + lch * 16);

    float c[4][8][4] = {};

#define LOAD_STAGE(st, kt_) do {                                               \
        uint32_t s = sb + (uint32_t)(st) * STAGE_BYTES + sRow;                 \
        _Pragma("unroll")                                                      \
        for (int i_ = 0; i_ < 4; i_++) {                                       \
            size_t gA_ = (size_t)(m0 + lrow + i_ * 64) * K_ + (kt_) + lch * 8; \
            cp16(s + T_AHI + (uint32_t)(i_ * 64 * LDAB), g_Ahi + gA_);         \
            cp16(s + T_ALO + (uint32_t)(i_ * 64 * LDAB), g_Alo + gA_);         \
        }                                                                      \
        _Pragma("unroll")                                                      \
        for (int i_ = 0; i_ < 2; i_++) {                                       \
            size_t gW_ = (size_t)(n0 + lrow + i_ * 64) * K_ + (kt_) + lch * 8; \
            cp16(s + T_W + (uint32_t)(i_ * 64 * LDAB), WT + gW_);              \
        }                                                                      \
        CP_COMMIT();                                                           \
    } while (0)

    LOAD_STAGE(0, 0);
    LOAD_STAGE(1, BKg);

    for (int t = 0; t < NTg; t++) {
        if (t < NTg - 1) CP_WAIT1(); else CP_WAIT0();
        __syncthreads();
        if (t + 2 < NTg) LOAD_STAGE((t + 2) % NSTAGE, (t + 2) * BKg);

        const uint32_t bufb = sb + (uint32_t)(t % NSTAGE) * STAGE_BYTES;
#pragma unroll
        for (int ks = 0; ks < 2; ks++) {
            const uint32_t kb = (uint32_t)(ks * 32 + (lane >> 4) * 16);
            uint32_t ah[4][4], al[4][4], bw[4][4];
#pragma unroll
            for (int mi = 0; mi < 4; mi++) {
                uint32_t r = (uint32_t)((wm * 64 + mi * 16 + (lane & 15)) * LDAB) + kb;
                LDSM4(ah[mi], bufb + T_AHI + r);
                LDSM4(al[mi], bufb + T_ALO + r);
            }
#pragma unroll
            for (int nj = 0; nj < 4; nj++) {
                uint32_t r = (uint32_t)((wn * 64 + nj * 16 + (lane & 15)) * LDAB) + kb;
                LDSM4(bw[nj], bufb + T_W + r);
            }
#pragma unroll
            for (int mi = 0; mi < 4; mi++)
#pragma unroll
                for (int nj = 0; nj < 4; nj++) {
                    uint32_t f0[2] = {bw[nj][0], bw[nj][2]};
                    uint32_t f1[2] = {bw[nj][1], bw[nj][3]};
                    MMA_F16(c[mi][2 * nj],     ah[mi], f0);
                    MMA_F16(c[mi][2 * nj],     al[mi], f0);
                    MMA_F16(c[mi][2 * nj + 1], ah[mi], f1);
                    MMA_F16(c[mi][2 * nj + 1], al[mi], f1);
                }
        }
        __syncthreads();
    }
#undef LOAD_STAGE

    // epilogue: + bias, fp32 store, optional per-row sumsq via atomics
#pragma unroll
    for (int mi = 0; mi < 4; mi++) {
        const int row = m0 + wm * 64 + mi * 16 + (lane >> 2);
        float p0 = 0.f, p1 = 0.f;
#pragma unroll
        for (int ni = 0; ni < 8; ni++) {
            const int col = n0 + wn * 64 + ni * 8 + 2 * (lane & 3);
            float2 bv = *(const float2*)(bias + col);
            float2 v0 = make_float2(c[mi][ni][0] + bv.x, c[mi][ni][1] + bv.y);
            float2 v1 = make_float2(c[mi][ni][2] + bv.x, c[mi][ni][3] + bv.y);
            *(float2*)(Y + (size_t)row * N + col)       = v0;
            *(float2*)(Y + (size_t)(row + 8) * N + col) = v1;
            p0 += v0.x * v0.x + v0.y * v0.y;
            p1 += v1.x * v1.x + v1.y * v1.y;
        }
        if (do_rsum) {
            // reduce across the 4 lanes sharing this row (lane&3 = 0..3)
            p0 += __shfl_xor_sync(0xffffffffu, p0, 1);
            p0 += __shfl_xor_sync(0xffffffffu, p0, 2);
            p1 += __shfl_xor_sync(0xffffffffu, p1, 1);
            p1 += __shfl_xor_sync(0xffffffffu, p1, 2);
            if ((lane & 3) == 0) {
                atomicAdd(&g_rsum[row], p0);
                atomicAdd(&g_rsum[row + 8], p1);
            }
        }
    }
}

// ---------------- kernel 5: T5 RMS-norm + ReLU (in place, final) ------------
__global__ void rms_kernel(float* __restrict__ Y, const float* __restrict__ gw, int N)
{
    const int row = blockIdx.x;
    const int t = threadIdx.x;
    float4* p = (float4*)(Y + (size_t)row * N);
    const float4 v = p[t];
    float ss = v.x * v.x + v.y * v.y + v.z * v.z + v.w * v.w;
#pragma unroll
    for (int o = 16; o; o >>= 1) ss += __shfl_xor_sync(0xffffffffu, ss, o);
    __shared__ float ws[8];
    if ((t & 31) == 0) ws[t >> 5] = ss;
    __syncthreads();
    float tot = 0.f;
    const int nw = blockDim.x >> 5;
    for (int i = 0; i < nw; i++) tot += ws[i];
    const float r = rsqrtf(tot / (float)N + 1e-12f);
    const float4 g4 = ((const float4*)gw)[t];
    float4 o4;
    o4.x = fmaxf(g4.x * v.x * r, 0.f);
    o4.y = fmaxf(g4.y * v.y * r, 0.f);
    o4.z = fmaxf(g4.z * v.z * r, 0.f);
    o4.w = fmaxf(g4.w * v.w * r, 0.f);
    p[t] = o4;
}

// ---------------- launch ----------------------------------------------------
extern "C" void kernel_launch(void* const* d_in, const int* in_sizes, int n_in,
                              void* d_out, int out_size)
{
    (void)in_sizes; (void)n_in; (void)out_size;
    const float* table  = (const float*)d_in[0];
    const float* a_simi = (const float*)d_in[1];
    const float* t_simi = (const float*)d_in[2];
    const float* adj    = (const float*)d_in[3];
    const float* W1     = (const float*)d_in[4];
    const float* b1     = (const float*)d_in[5];
    const float* g1     = (const float*)d_in[6];
    const float* W2     = (const float*)d_in[7];
    const float* b2     = (const float*)d_in[8];
    const float* g2     = (const float*)d_in[9];
    float* out = (float*)d_out;

    static bool attr_set = false;
    if (!attr_set) {
        cudaFuncSetAttribute(gemm_mma_kernel,
                             cudaFuncAttributeMaxDynamicSharedMemorySize, SMEM_G);
        attr_set = true;
    }

    const int nconv = K_ * (N1_ + N2_);
    conv_w_kernel<<<(nconv + 255) / 256, 256>>>(W1, W2);   // also zeroes g_rsum

    // layer 1: gather(table) -> GEMM1 (+rsum) -> rfac
    gather_kernel<<<M_, 192>>>(table, a_simi, t_simi, adj, 0, g1);
    gemm_mma_kernel<<<dim3(N1_ / BNg, M_ / BMg), 256, SMEM_G>>>(0, b1, nullptr, N1_, 1);
    rfac_kernel<<<(M_ + 255) / 256, 256>>>();

    // layer 2: gather(norm(Y)) -> GEMM2 -> rms
    gather_kernel<<<M_, 192>>>(nullptr, a_simi, t_simi, adj, 1, g1);
    gemm_mma_kernel<<<dim3(N2_ / BNg, M_ / BMg), 256, SMEM_G>>>(1, b2, out, N2_, 0);
    rms_kernel<<<M_, N2_ / 4>>>(out, g2, N2_);
}

// round 9
// speedup vs baseline: 2.6957x; 1.4786x over previous
#include <cuda_runtime.h>
#include <cuda_fp16.h>
#include <cstdint>

// ---------------------------------------------------------------- shapes
#define B_  8
#define S_  96
#define D_  768
#define M_  (B_ * S_ * S_)   // 73728 rows
#define K_  768
#define N1_ 768
#define N2_ 256

// GEMM tiling (mma.sync path, base ISA only)
#define BMg 256              // CTA M
#define BNg 128              // CTA N
#define BKg 32               // k per stage
#define NTg (K_ / BKg)       // 24 k-tiles
#define LDAB 80              // bytes per smem row (32 fp16 = 64B data + 16B pad)
// per-stage smem byte offsets
#define T_A 0                // 256 rows * 80B = 20480
#define T_W 20480            // 128 rows * 80B = 10240
#define STAGE_BYTES 30720
#define NSTAGE 3
#define SMEM_G (NSTAGE * STAGE_BYTES)   // 92160 B

// ---------------- scratch (static device globals; no allocations) ----------
static __device__ float  g_Y[(size_t)M_ * N1_];        // GEMM1 out (pre-norm)
static __device__ float  g_rsum[M_];                   // per-row sum of squares
static __device__ float  g_rfac[M_];                   // rsqrt factors
static __device__ __half g_A[(size_t)M_ * K_];         // gather out, fp16
static __device__ __half g_W1T[(size_t)N1_ * K_];      // W^T, k-contiguous, fp16
static __device__ __half g_W2T[(size_t)N2_ * K_];

// ---------------------------------------------------------------- helpers
__device__ __forceinline__ uint32_t smem_u32(const void* p) {
    uint32_t a;
    asm("{ .reg .u64 t; cvta.to.shared.u64 t, %1; cvt.u32.u64 %0, t; }" : "=r"(a) : "l"(p));
    return a;
}

__device__ __forceinline__ void cp16(uint32_t s, const void* g) {
    asm volatile("cp.async.cg.shared.global [%0], [%1], 16;" :: "r"(s), "l"(g));
}
#define CP_COMMIT() asm volatile("cp.async.commit_group;" ::: "memory")
#define CP_WAIT1()  asm volatile("cp.async.wait_group 1;" ::: "memory")
#define CP_WAIT0()  asm volatile("cp.async.wait_group 0;" ::: "memory")

#define LDSM4(r, addr) \
    asm volatile("ldmatrix.sync.aligned.m8n8.x4.shared.b16 {%0,%1,%2,%3}, [%4];" \
        : "=r"((r)[0]), "=r"((r)[1]), "=r"((r)[2]), "=r"((r)[3]) : "r"(addr))

#define MMA_F16(Cv, Av, Bv) asm volatile( \
    "mma.sync.aligned.m16n8k16.row.col.f32.f16.f16.f32 " \
    "{%0,%1,%2,%3}, {%4,%5,%6,%7}, {%8,%9}, {%0,%1,%2,%3};\n" \
    : "+f"((Cv)[0]), "+f"((Cv)[1]), "+f"((Cv)[2]), "+f"((Cv)[3]) \
    : "r"((Av)[0]), "r"((Av)[1]), "r"((Av)[2]), "r"((Av)[3]), \
      "r"((Bv)[0]), "r"((Bv)[1]))

// ---------------- kernel 1: fp16 + transpose weights, zero rsum -------------
__global__ void conv_w_kernel(const float* __restrict__ W1,
                              const float* __restrict__ W2)
{
    int i = blockIdx.x * blockDim.x + threadIdx.x;
    const int n1 = K_ * N1_;
    const int n2 = K_ * N2_;
    if (i < M_) g_rsum[i] = 0.f;
    if (i < n1) {
        int k = i / N1_, n = i % N1_;
        g_W1T[(size_t)n * K_ + k] = __float2half(W1[i]);
    } else if (i < n1 + n2) {
        int j = i - n1;
        int k = j / N2_, n = j % N2_;
        g_W2T[(size_t)n * K_ + k] = __float2half(W2[j]);
    }
}

// ---------------- kernel 2: gather stencil (+opt norm) -> fp16 --------------
__device__ __forceinline__ void fma4(float4& r, float s, const float4 v) {
    r.x += s * v.x; r.y += s * v.y; r.z += s * v.z; r.w += s * v.w;
}

// load one float4 from row `src`; if use_norm, apply relu(g * x * g_rfac[src]).
__device__ __forceinline__ float4 load4(const float* __restrict__ h, int src, int t,
                                        int use_norm, const float4 g4)
{
    float4 v = ((const float4*)(h + (size_t)src * D_))[t];
    if (use_norm) {
        const float r = g_rfac[src];
        v.x = fmaxf(g4.x * v.x * r, 0.f);
        v.y = fmaxf(g4.y * v.y * r, 0.f);
        v.z = fmaxf(g4.z * v.z * r, 0.f);
        v.w = fmaxf(g4.w * v.w * r, 0.f);
    }
    return v;
}

__global__ void gather_kernel(const float* __restrict__ hext,
                              const float* __restrict__ a_simi,
                              const float* __restrict__ t_simi,
                              const float* __restrict__ adj,
                              int use_norm,
                              const float* __restrict__ gw)
{
    const float* h = hext ? hext : g_Y;
    const int idx = blockIdx.x;               // (b*S + l)*S + k
    const int k = idx % S_;
    const int l = (idx / S_) % S_;
    const int b = idx / (S_ * S_);
    const int t = threadIdx.x;                // 0..191

    float4 g4 = make_float4(1.f, 1.f, 1.f, 1.f);
    if (use_norm) g4 = ((const float4*)gw)[t];

    const float4 cv = load4(h, idx, t, use_norm, g4);
    const float4 dv = load4(h, (b * S_ + l) * S_ + l, t, use_norm, g4);
    const float adjv = adj[(size_t)(b * S_ + l) * S_ + k];

    float4 r;
    r.x = 2.f * cv.x + adjv * dv.x;
    r.y = 2.f * cv.y + adjv * dv.y;
    r.z = 2.f * cv.z + adjv * dv.z;
    r.w = 2.f * cv.w + adjv * dv.w;

    if (k > 0)      fma4(r, t_simi[b * S_ + k - 1], load4(h, idx - 1,  t, use_norm, g4));
    if (k < S_ - 1) fma4(r, t_simi[b * S_ + k + 1], load4(h, idx + 1,  t, use_norm, g4));
    if (l > 0)      fma4(r, a_simi[b * S_ + l - 1], load4(h, idx - S_, t, use_norm, g4));
    if (l < S_ - 1) fma4(r, a_simi[b * S_ + l + 1], load4(h, idx + S_, t, use_norm, g4));

    // single-rounded fp16 store (8B vectorized)
    __half2 v01, v23;
    v01.x = __float2half(r.x); v01.y = __float2half(r.y);
    v23.x = __float2half(r.z); v23.y = __float2half(r.w);
    size_t o = (size_t)idx * D_ + t * 4;
    __half2* pa = (__half2*)(g_A + o);
    pa[0] = v01;
    pa[1] = v23;
}

// ---------------- kernel 3: rfac = rsqrt(rsum/D + eps) ----------------------
__global__ void rfac_kernel()
{
    int i = blockIdx.x * blockDim.x + threadIdx.x;
    if (i < M_) g_rfac[i] = rsqrtf(g_rsum[i] * (1.f / (float)N1_) + 1e-12f);
}

// ---------------- kernel 4: mma.sync fp16 GEMM + bias -----------------------
// C = A@W^T + bias; optional per-row sum-of-squares accumulation.
// CTA tile 256x128x32, 256 thr (8 warps 4Mx2N, warp tile 64x64),
// 3-stage cp.async pipeline, ldmatrix.x4, 80B-padded rows.
__global__ void __launch_bounds__(256, 1)
gemm_mma_kernel(int layer, const float* __restrict__ bias,
                float* __restrict__ Yext, int N, int do_rsum)
{
    extern __shared__ __align__(128) char smem[];
    const __half* __restrict__ WT = layer ? g_W2T : g_W1T;
    float* Y = Yext ? Yext : g_Y;

    const int tid  = threadIdx.x;
    const int wid  = tid >> 5;
    const int lane = tid & 31;
    const int wm   = wid & 3;            // warp m index (0..3), 64 rows each
    const int wn   = wid >> 2;           // warp n index (0..1), 64 cols each
    const int m0 = blockIdx.y * BMg;
    const int n0 = blockIdx.x * BNg;
    const uint32_t sb = smem_u32(smem);

    const int lrow = tid >> 2;           // 0..63
    const int lch  = tid & 3;            // 16B chunk in 64B k-row
    const uint32_t sRow = (uint32_t)(lrow * LDAB + lch * 16);

    float c[4][8][4] = {};

#define LOAD_STAGE(st, kt_) do {                                               \
        uint32_t s = sb + (uint32_t)(st) * STAGE_BYTES + sRow;                 \
        _Pragma("unroll")                                                      \
        for (int i_ = 0; i_ < 4; i_++) {                                       \
            size_t gA_ = (size_t)(m0 + lrow + i_ * 64) * K_ + (kt_) + lch * 8; \
            cp16(s + T_A + (uint32_t)(i_ * 64 * LDAB), g_A + gA_);             \
        }                                                                      \
        _Pragma("unroll")                                                      \
        for (int i_ = 0; i_ < 2; i_++) {                                       \
            size_t gW_ = (size_t)(n0 + lrow + i_ * 64) * K_ + (kt_) + lch * 8; \
            cp16(s + T_W + (uint32_t)(i_ * 64 * LDAB), WT + gW_);              \
        }                                                                      \
        CP_COMMIT();                                                           \
    } while (0)

    LOAD_STAGE(0, 0);
    LOAD_STAGE(1, BKg);

    for (int t = 0; t < NTg; t++) {
        if (t < NTg - 1) CP_WAIT1(); else CP_WAIT0();
        __syncthreads();
        if (t + 2 < NTg) LOAD_STAGE((t + 2) % NSTAGE, (t + 2) * BKg);

        const uint32_t bufb = sb + (uint32_t)(t % NSTAGE) * STAGE_BYTES;
#pragma unroll
        for (int ks = 0; ks < 2; ks++) {
            const uint32_t kb = (uint32_t)(ks * 32 + (lane >> 4) * 16);
            uint32_t aw[4][4], bw[4][4];
#pragma unroll
            for (int mi = 0; mi < 4; mi++) {
                uint32_t r = (uint32_t)((wm * 64 + mi * 16 + (lane & 15)) * LDAB) + kb;
                LDSM4(aw[mi], bufb + T_A + r);
            }
#pragma unroll
            for (int nj = 0; nj < 4; nj++) {
                uint32_t r = (uint32_t)((wn * 64 + nj * 16 + (lane & 15)) * LDAB) + kb;
                LDSM4(bw[nj], bufb + T_W + r);
            }
#pragma unroll
            for (int mi = 0; mi < 4; mi++)
#pragma unroll
                for (int nj = 0; nj < 4; nj++) {
                    uint32_t f0[2] = {bw[nj][0], bw[nj][2]};
                    uint32_t f1[2] = {bw[nj][1], bw[nj][3]};
                    MMA_F16(c[mi][2 * nj],     aw[mi], f0);
                    MMA_F16(c[mi][2 * nj + 1], aw[mi], f1);
                }
        }
        __syncthreads();
    }
#undef LOAD_STAGE

    // epilogue: + bias, fp32 store, optional per-row sumsq via atomics
#pragma unroll
    for (int mi = 0; mi < 4; mi++) {
        const int row = m0 + wm * 64 + mi * 16 + (lane >> 2);
        float p0 = 0.f, p1 = 0.f;
#pragma unroll
        for (int ni = 0; ni < 8; ni++) {
            const int col = n0 + wn * 64 + ni * 8 + 2 * (lane & 3);
            float2 bv = *(const float2*)(bias + col);
            float2 v0 = make_float2(c[mi][ni][0] + bv.x, c[mi][ni][1] + bv.y);
            float2 v1 = make_float2(c[mi][ni][2] + bv.x, c[mi][ni][3] + bv.y);
            *(float2*)(Y + (size_t)row * N + col)       = v0;
            *(float2*)(Y + (size_t)(row + 8) * N + col) = v1;
            p0 += v0.x * v0.x + v0.y * v0.y;
            p1 += v1.x * v1.x + v1.y * v1.y;
        }
        if (do_rsum) {
            p0 += __shfl_xor_sync(0xffffffffu, p0, 1);
            p0 += __shfl_xor_sync(0xffffffffu, p0, 2);
            p1 += __shfl_xor_sync(0xffffffffu, p1, 1);
            p1 += __shfl_xor_sync(0xffffffffu, p1, 2);
            if ((lane & 3) == 0) {
                atomicAdd(&g_rsum[row], p0);
                atomicAdd(&g_rsum[row + 8], p1);
            }
        }
    }
}

// ---------------- kernel 5: T5 RMS-norm + ReLU (in place, final) ------------
__global__ void rms_kernel(float* __restrict__ Y, const float* __restrict__ gw, int N)
{
    const int row = blockIdx.x;
    const int t = threadIdx.x;
    float4* p = (float4*)(Y + (size_t)row * N);
    const float4 v = p[t];
    float ss = v.x * v.x + v.y * v.y + v.z * v.z + v.w * v.w;
#pragma unroll
    for (int o = 16; o; o >>= 1) ss += __shfl_xor_sync(0xffffffffu, ss, o);
    __shared__ float ws[8];
    if ((t & 31) == 0) ws[t >> 5] = ss;
    __syncthreads();
    float tot = 0.f;
    const int nw = blockDim.x >> 5;
    for (int i = 0; i < nw; i++) tot += ws[i];
    const float r = rsqrtf(tot / (float)N + 1e-12f);
    const float4 g4 = ((const float4*)gw)[t];
    float4 o4;
    o4.x = fmaxf(g4.x * v.x * r, 0.f);
    o4.y = fmaxf(g4.y * v.y * r, 0.f);
    o4.z = fmaxf(g4.z * v.z * r, 0.f);
    o4.w = fmaxf(g4.w * v.w * r, 0.f);
    p[t] = o4;
}

// ---------------- launch ----------------------------------------------------
extern "C" void kernel_launch(void* const* d_in, const int* in_sizes, int n_in,
                              void* d_out, int out_size)
{
    (void)in_sizes; (void)n_in; (void)out_size;
    const float* table  = (const float*)d_in[0];
    const float* a_simi = (const float*)d_in[1];
    const float* t_simi = (const float*)d_in[2];
    const float* adj    = (const float*)d_in[3];
    const float* W1     = (const float*)d_in[4];
    const float* b1     = (const float*)d_in[5];
    const float* g1     = (const float*)d_in[6];
    const float* W2     = (const float*)d_in[7];
    const float* b2     = (const float*)d_in[8];
    const float* g2     = (const float*)d_in[9];
    float* out = (float*)d_out;

    static bool attr_set = false;
    if (!attr_set) {
        cudaFuncSetAttribute(gemm_mma_kernel,
                             cudaFuncAttributeMaxDynamicSharedMemorySize, SMEM_G);
        attr_set = true;
    }

    const int nconv = K_ * (N1_ + N2_);
    conv_w_kernel<<<(nconv + 255) / 256, 256>>>(W1, W2);   // also zeroes g_rsum

    // layer 1: gather(table) -> GEMM1 (+rsum) -> rfac
    gather_kernel<<<M_, 192>>>(table, a_simi, t_simi, adj, 0, g1);
    gemm_mma_kernel<<<dim3(N1_ / BNg, M_ / BMg), 256, SMEM_G>>>(0, b1, nullptr, N1_, 1);
    rfac_kernel<<<(M_ + 255) / 256, 256>>>();

    // layer 2: gather(norm(Y)) -> GEMM2 -> rms
    gather_kernel<<<M_, 192>>>(nullptr, a_simi, t_simi, adj, 1, g1);
    gemm_mma_kernel<<<dim3(N2_ / BNg, M_ / BMg), 256, SMEM_G>>>(1, b2, out, N2_, 0);
    rms_kernel<<<M_, N2_ / 4>>>(out, g2, N2_);
}

// round 11
// speedup vs baseline: 2.7492x; 1.0199x over previous
#include <cuda_runtime.h>
#include <cuda_fp16.h>
#include <cstdint>

// ---------------------------------------------------------------- shapes
#define B_  8
#define S_  96
#define D_  768
#define M_  (B_ * S_ * S_)   // 73728 rows
#define K_  768
#define N1_ 768
#define N2_ 256

// GEMM tiling (mma.sync path, base ISA only)
#define BKg 32               // k per stage
#define NTg (K_ / BKg)       // 24 k-tiles
#define LDAB 80              // bytes per smem row (32 fp16 = 64B + 16B pad)
// GEMM1: CTA 256x128
#define BM1 256
#define BN1 128
#define T1_A 0               // 256 rows * 80B = 20480
#define T1_W 20480           // 128 rows * 80B = 10240
// GEMM2: CTA 128x256 (full N in one CTA -> fused RMS)
#define BM2 128
#define BN2 256
#define T2_A 0               // 128 rows * 80B = 10240
#define T2_W 10240           // 256 rows * 80B = 20480
#define STAGE_BYTES 30720
#define NSTAGE 3
#define SMEM_G (NSTAGE * STAGE_BYTES)   // 92160 B

// ---------------- scratch (static device globals; no allocations) ----------
// RULE: these symbols are referenced ONLY from device code, never passed as
// kernel arguments from host (host-side shadow address bug, rounds 7 & 10).
static __device__ __half g_Yh[(size_t)M_ * N1_];       // GEMM1 out (pre-norm), fp16
static __device__ float  g_rsum[M_];                   // per-row sum of squares
static __device__ float  g_rfac[M_];                   // rsqrt factors
static __device__ __half g_A[(size_t)M_ * K_];         // gather out, fp16
static __device__ __half g_W1T[(size_t)N1_ * K_];      // W^T, k-contiguous, fp16
static __device__ __half g_W2T[(size_t)N2_ * K_];

// ---------------------------------------------------------------- helpers
__device__ __forceinline__ uint32_t smem_u32(const void* p) {
    uint32_t a;
    asm("{ .reg .u64 t; cvta.to.shared.u64 t, %1; cvt.u32.u64 %0, t; }" : "=r"(a) : "l"(p));
    return a;
}

__device__ __forceinline__ void cp16(uint32_t s, const void* g) {
    asm volatile("cp.async.cg.shared.global [%0], [%1], 16;" :: "r"(s), "l"(g));
}
#define CP_COMMIT() asm volatile("cp.async.commit_group;" ::: "memory")
#define CP_WAIT1()  asm volatile("cp.async.wait_group 1;" ::: "memory")
#define CP_WAIT0()  asm volatile("cp.async.wait_group 0;" ::: "memory")

#define LDSM4(r, addr) \
    asm volatile("ldmatrix.sync.aligned.m8n8.x4.shared.b16 {%0,%1,%2,%3}, [%4];" \
        : "=r"((r)[0]), "=r"((r)[1]), "=r"((r)[2]), "=r"((r)[3]) : "r"(addr))

#define MMA_F16(Cv, Av, Bv) asm volatile( \
    "mma.sync.aligned.m16n8k16.row.col.f32.f16.f16.f32 " \
    "{%0,%1,%2,%3}, {%4,%5,%6,%7}, {%8,%9}, {%0,%1,%2,%3};\n" \
    : "+f"((Cv)[0]), "+f"((Cv)[1]), "+f"((Cv)[2]), "+f"((Cv)[3]) \
    : "r"((Av)[0]), "r"((Av)[1]), "r"((Av)[2]), "r"((Av)[3]), \
      "r"((Bv)[0]), "r"((Bv)[1]))

// ---------------- kernel 1: coalesced W -> W^T fp16 transpose ---------------
// 32x32 tiles via smem; block 32x8, 4 rows per thread. Destination selected
// INSIDE device code (which=0 -> g_W1T, which=1 -> g_W2T).
__global__ void trans_kernel(const float* __restrict__ W, int which, int N)
{
    __half* __restrict__ WT = which ? g_W2T : g_W1T;
    __shared__ float tile[32][33];
    const int n0 = blockIdx.x * 32, k0 = blockIdx.y * 32;
    const int tx = threadIdx.x, ty = threadIdx.y;
#pragma unroll
    for (int r = 0; r < 4; r++)
        tile[ty + 8 * r][tx] = W[(size_t)(k0 + ty + 8 * r) * N + n0 + tx];
    __syncthreads();
#pragma unroll
    for (int r = 0; r < 4; r++)
        WT[(size_t)(n0 + ty + 8 * r) * K_ + k0 + tx] = __float2half(tile[tx][ty + 8 * r]);
}

// ---------------- kernel 2: rotating-register gather stencil ----------------
__device__ __forceinline__ void fma4(float4& r, float s, const float4 v) {
    r.x += s * v.x; r.y += s * v.y; r.z += s * v.z; r.w += s * v.w;
}

// load one float4 of row `src`; hf!=null -> fp32 table, else fp16 g_Yh.
// if use_norm, apply relu(g * x * g_rfac[src]).
__device__ __forceinline__ float4 loadrow(const float* __restrict__ hf, int src, int t,
                                          int use_norm, const float4 g4)
{
    float4 v;
    if (hf) {
        v = ((const float4*)(hf + (size_t)src * D_))[t];
    } else {
        uint2 u = *((const uint2*)(g_Yh + (size_t)src * D_) + t);
        __half2 a = *(__half2*)&u.x;
        __half2 b = *(__half2*)&u.y;
        v.x = __half2float(a.x); v.y = __half2float(a.y);
        v.z = __half2float(b.x); v.w = __half2float(b.y);
    }
    if (use_norm) {
        const float r = g_rfac[src];
        v.x = fmaxf(g4.x * v.x * r, 0.f);
        v.y = fmaxf(g4.y * v.y * r, 0.f);
        v.z = fmaxf(g4.z * v.z * r, 0.f);
        v.w = fmaxf(g4.w * v.w * r, 0.f);
    }
    return v;
}

// One block per (b,l); iterate k=0..S-1 with prev/cur/next rotation so each
// own-slab row is read once. Also zeroes g_rsum on the layer-1 pass.
__global__ void gather_kernel(const float* __restrict__ table,
                              const float* __restrict__ a_simi,
                              const float* __restrict__ t_simi,
                              const float* __restrict__ adj,
                              int use_norm, const float* __restrict__ gw)
{
    const int bl = blockIdx.x;            // b*S + l
    const int b = bl / S_, l = bl % S_;
    const int t = threadIdx.x;            // 0..191 (float4 over D)
    const int base = bl * S_;             // row index of (b,l,0)

    float4 g4 = make_float4(1.f, 1.f, 1.f, 1.f);
    if (use_norm) g4 = ((const float4*)gw)[t];

    const float au = (l > 0)      ? a_simi[b * S_ + l - 1] : 0.f;
    const float ad = (l < S_ - 1) ? a_simi[b * S_ + l + 1] : 0.f;

    const float4 diag = loadrow(table, base + l, t, use_norm, g4);
    float4 prev = make_float4(0.f, 0.f, 0.f, 0.f);
    float4 cur  = loadrow(table, base,     t, use_norm, g4);
    float4 nxt  = loadrow(table, base + 1, t, use_norm, g4);

    for (int k = 0; k < S_; k++) {
        const int idx = base + k;
        const float adjv = adj[idx];
        float4 r;
        r.x = 2.f * cur.x + adjv * diag.x;
        r.y = 2.f * cur.y + adjv * diag.y;
        r.z = 2.f * cur.z + adjv * diag.z;
        r.w = 2.f * cur.w + adjv * diag.w;
        if (k > 0)      fma4(r, t_simi[b * S_ + k - 1], prev);
        if (k < S_ - 1) fma4(r, t_simi[b * S_ + k + 1], nxt);
        if (l > 0)      fma4(r, au, loadrow(table, idx - S_, t, use_norm, g4));
        if (l < S_ - 1) fma4(r, ad, loadrow(table, idx + S_, t, use_norm, g4));

        __half2 v01, v23;
        v01.x = __float2half(r.x); v01.y = __float2half(r.y);
        v23.x = __float2half(r.z); v23.y = __float2half(r.w);
        __half2* pa = (__half2*)(g_A + (size_t)idx * D_) + 2 * t;
        pa[0] = v01;
        pa[1] = v23;
        if (!use_norm && t == 0) g_rsum[idx] = 0.f;

        prev = cur; cur = nxt;
        nxt = (k + 2 < S_) ? loadrow(table, idx + 2, t, use_norm, g4)
                           : make_float4(0.f, 0.f, 0.f, 0.f);
    }
}

// ---------------- kernel 3: rfac = rsqrt(rsum/D + eps) ----------------------
__global__ void rfac_kernel()
{
    int i = blockIdx.x * blockDim.x + threadIdx.x;
    if (i < M_) g_rfac[i] = rsqrtf(g_rsum[i] * (1.f / (float)N1_) + 1e-12f);
}

// ---------------- kernel 4: GEMM1  Yh = fp16(A@W1^T + b1), rsum accumulation -
// CTA 256x128x32, 256 thr (8 warps 4Mx2N, warp 64x64), 3-stage cp.async.
__global__ void __launch_bounds__(256, 1)
gemm1_kernel(const float* __restrict__ bias)
{
    extern __shared__ __align__(128) char smem[];
    const int tid  = threadIdx.x;
    const int wid  = tid >> 5;
    const int lane = tid & 31;
    const int wm   = wid & 3;            // 0..3, 64 rows each
    const int wn   = wid >> 2;           // 0..1, 64 cols each
    const int m0 = blockIdx.y * BM1;
    const int n0 = blockIdx.x * BN1;
    const uint32_t sb = smem_u32(smem);

    const int lrow = tid >> 2;
    const int lch  = tid & 3;
    const uint32_t sRow = (uint32_t)(lrow * LDAB + lch * 16);

    float c[4][8][4] = {};

#define LOAD_STAGE1(st, kt_) do {                                              \
        uint32_t s = sb + (uint32_t)(st) * STAGE_BYTES + sRow;                 \
        _Pragma("unroll")                                                      \
        for (int i_ = 0; i_ < 4; i_++) {                                       \
            size_t gA_ = (size_t)(m0 + lrow + i_ * 64) * K_ + (kt_) + lch * 8; \
            cp16(s + T1_A + (uint32_t)(i_ * 64 * LDAB), g_A + gA_);            \
        }                                                                      \
        _Pragma("unroll")                                                      \
        for (int i_ = 0; i_ < 2; i_++) {                                       \
            size_t gW_ = (size_t)(n0 + lrow + i_ * 64) * K_ + (kt_) + lch * 8; \
            cp16(s + T1_W + (uint32_t)(i_ * 64 * LDAB), g_W1T + gW_);          \
        }                                                                      \
        CP_COMMIT();                                                           \
    } while (0)

    LOAD_STAGE1(0, 0);
    LOAD_STAGE1(1, BKg);

    for (int t = 0; t < NTg; t++) {
        if (t < NTg - 1) CP_WAIT1(); else CP_WAIT0();
        __syncthreads();
        if (t + 2 < NTg) LOAD_STAGE1((t + 2) % NSTAGE, (t + 2) * BKg);

        const uint32_t bufb = sb + (uint32_t)(t % NSTAGE) * STAGE_BYTES;
#pragma unroll
        for (int ks = 0; ks < 2; ks++) {
            const uint32_t kb = (uint32_t)(ks * 32 + (lane >> 4) * 16);
            uint32_t aw[4][4], bw[4][4];
#pragma unroll
            for (int mi = 0; mi < 4; mi++) {
                uint32_t r = (uint32_t)((wm * 64 + mi * 16 + (lane & 15)) * LDAB) + kb;
                LDSM4(aw[mi], bufb + T1_A + r);
            }
#pragma unroll
            for (int nj = 0; nj < 4; nj++) {
                uint32_t r = (uint32_t)((wn * 64 + nj * 16 + (lane & 15)) * LDAB) + kb;
                LDSM4(bw[nj], bufb + T1_W + r);
            }
#pragma unroll
            for (int mi = 0; mi < 4; mi++)
#pragma unroll
                for (int nj = 0; nj < 4; nj++) {
                    uint32_t f0[2] = {bw[nj][0], bw[nj][2]};
                    uint32_t f1[2] = {bw[nj][1], bw[nj][3]};
                    MMA_F16(c[mi][2 * nj],     aw[mi], f0);
                    MMA_F16(c[mi][2 * nj + 1], aw[mi], f1);
                }
        }
        __syncthreads();
    }
#undef LOAD_STAGE1

    // epilogue: + bias, fp16 store, per-row sumsq via atomics
#pragma unroll
    for (int mi = 0; mi < 4; mi++) {
        const int row = m0 + wm * 64 + mi * 16 + (lane >> 2);
        float p0 = 0.f, p1 = 0.f;
#pragma unroll
        for (int ni = 0; ni < 8; ni++) {
            const int col = n0 + wn * 64 + ni * 8 + 2 * (lane & 3);
            float2 bv = *(const float2*)(bias + col);
            float2 v0 = make_float2(c[mi][ni][0] + bv.x, c[mi][ni][1] + bv.y);
            float2 v1 = make_float2(c[mi][ni][2] + bv.x, c[mi][ni][3] + bv.y);
            *(__half2*)(g_Yh + (size_t)row * N1_ + col)       = __floats2half2_rn(v0.x, v0.y);
            *(__half2*)(g_Yh + (size_t)(row + 8) * N1_ + col) = __floats2half2_rn(v1.x, v1.y);
            p0 += v0.x * v0.x + v0.y * v0.y;
            p1 += v1.x * v1.x + v1.y * v1.y;
        }
        p0 += __shfl_xor_sync(0xffffffffu, p0, 1);
        p0 += __shfl_xor_sync(0xffffffffu, p0, 2);
        p1 += __shfl_xor_sync(0xffffffffu, p1, 1);
        p1 += __shfl_xor_sync(0xffffffffu, p1, 2);
        if ((lane & 3) == 0) {
            atomicAdd(&g_rsum[row], p0);
            atomicAdd(&g_rsum[row + 8], p1);
        }
    }
}

// ---------------- kernel 5: GEMM2 + fused T5 RMS-norm + ReLU ----------------
// CTA 128x256x32 (full N2 in one CTA), 256 thr (8 warps 2Mx4N, warp 64x64).
__global__ void __launch_bounds__(256, 1)
gemm2_kernel(const float* __restrict__ bias, const float* __restrict__ gw,
             float* __restrict__ out)
{
    extern __shared__ __align__(128) char smem[];
    const int tid  = threadIdx.x;
    const int wid  = tid >> 5;
    const int lane = tid & 31;
    const int wm   = wid & 1;            // 0..1, 64 rows each
    const int wn   = wid >> 1;           // 0..3, 64 cols each
    const int m0 = blockIdx.x * BM2;
    const uint32_t sb = smem_u32(smem);

    const int lrow = tid >> 2;
    const int lch  = tid & 3;
    const uint32_t sRow = (uint32_t)(lrow * LDAB + lch * 16);

    float c[4][8][4] = {};

#define LOAD_STAGE2(st, kt_) do {                                              \
        uint32_t s = sb + (uint32_t)(st) * STAGE_BYTES + sRow;                 \
        _Pragma("unroll")                                                      \
        for (int i_ = 0; i_ < 2; i_++) {                                       \
            size_t gA_ = (size_t)(m0 + lrow + i_ * 64) * K_ + (kt_) + lch * 8; \
            cp16(s + T2_A + (uint32_t)(i_ * 64 * LDAB), g_A + gA_);            \
        }                                                                      \
        _Pragma("unroll")                                                      \
        for (int i_ = 0; i_ < 4; i_++) {                                       \
            size_t gW_ = (size_t)(lrow + i_ * 64) * K_ + (kt_) + lch * 8;      \
            cp16(s + T2_W + (uint32_t)(i_ * 64 * LDAB), g_W2T + gW_);          \
        }                                                                      \
        CP_COMMIT();                                                           \
    } while (0)

    LOAD_STAGE2(0, 0);
    LOAD_STAGE2(1, BKg);

    for (int t = 0; t < NTg; t++) {
        if (t < NTg - 1) CP_WAIT1(); else CP_WAIT0();
        __syncthreads();
        if (t + 2 < NTg) LOAD_STAGE2((t + 2) % NSTAGE, (t + 2) * BKg);

        const uint32_t bufb = sb + (uint32_t)(t % NSTAGE) * STAGE_BYTES;
#pragma unroll
        for (int ks = 0; ks < 2; ks++) {
            const uint32_t kb = (uint32_t)(ks * 32 + (lane >> 4) * 16);
            uint32_t aw[4][4], bw[4][4];
#pragma unroll
            for (int mi = 0; mi < 4; mi++) {
                uint32_t r = (uint32_t)((wm * 64 + mi * 16 + (lane & 15)) * LDAB) + kb;
                LDSM4(aw[mi], bufb + T2_A + r);
            }
#pragma unroll
            for (int nj = 0; nj < 4; nj++) {
                uint32_t r = (uint32_t)((wn * 64 + nj * 16 + (lane & 15)) * LDAB) + kb;
                LDSM4(bw[nj], bufb + T2_W + r);
            }
#pragma unroll
            for (int mi = 0; mi < 4; mi++)
#pragma unroll
                for (int nj = 0; nj < 4; nj++) {
                    uint32_t f0[2] = {bw[nj][0], bw[nj][2]};
                    uint32_t f1[2] = {bw[nj][1], bw[nj][3]};
                    MMA_F16(c[mi][2 * nj],     aw[mi], f0);
                    MMA_F16(c[mi][2 * nj + 1], aw[mi], f1);
                }
        }
        __syncthreads();
    }
#undef LOAD_STAGE2

    // ---- fused epilogue: row sumsq (cross-warp via smem), then norm+relu ----
    float* sp = (float*)smem;              // 128 rows x 4 wn partials
#pragma unroll
    for (int mi = 0; mi < 4; mi++) {
        const int prow = wm * 64 + mi * 16 + (lane >> 2);
        float p0 = 0.f, p1 = 0.f;
#pragma unroll
        for (int ni = 0; ni < 8; ni++) {
            const int col = wn * 64 + ni * 8 + 2 * (lane & 3);
            float2 bv = *(const float2*)(bias + col);
            float2 v0 = make_float2(c[mi][ni][0] + bv.x, c[mi][ni][1] + bv.y);
            float2 v1 = make_float2(c[mi][ni][2] + bv.x, c[mi][ni][3] + bv.y);
            p0 += v0.x * v0.x + v0.y * v0.y;
            p1 += v1.x * v1.x + v1.y * v1.y;
        }
        p0 += __shfl_xor_sync(0xffffffffu, p0, 1);
        p0 += __shfl_xor_sync(0xffffffffu, p0, 2);
        p1 += __shfl_xor_sync(0xffffffffu, p1, 1);
        p1 += __shfl_xor_sync(0xffffffffu, p1, 2);
        if ((lane & 3) == 0) {
            sp[prow * 4 + wn]       = p0;
            sp[(prow + 8) * 4 + wn] = p1;
        }
    }
    __syncthreads();
#pragma unroll
    for (int mi = 0; mi < 4; mi++) {
        const int prow = wm * 64 + mi * 16 + (lane >> 2);
        const float tot0 = sp[prow * 4] + sp[prow * 4 + 1] + sp[prow * 4 + 2] + sp[prow * 4 + 3];
        const float tot1 = sp[(prow + 8) * 4] + sp[(prow + 8) * 4 + 1] +
                           sp[(prow + 8) * 4 + 2] + sp[(prow + 8) * 4 + 3];
        const float r0 = rsqrtf(tot0 * (1.f / (float)N2_) + 1e-12f);
        const float r1 = rsqrtf(tot1 * (1.f / (float)N2_) + 1e-12f);
        const size_t row = (size_t)(m0 + prow);
#pragma unroll
        for (int ni = 0; ni < 8; ni++) {
            const int col = wn * 64 + ni * 8 + 2 * (lane & 3);
            float2 bv = *(const float2*)(bias + col);
            float2 gv = *(const float2*)(gw + col);
            float2 o0, o1;
            o0.x = fmaxf(gv.x * (c[mi][ni][0] + bv.x) * r0, 0.f);
            o0.y = fmaxf(gv.y * (c[mi][ni][1] + bv.y) * r0, 0.f);
            o1.x = fmaxf(gv.x * (c[mi][ni][2] + bv.x) * r1, 0.f);
            o1.y = fmaxf(gv.y * (c[mi][ni][3] + bv.y) * r1, 0.f);
            *(float2*)(out + row * N2_ + col)       = o0;
            *(float2*)(out + (row + 8) * N2_ + col) = o1;
        }
    }
}

// ---------------- launch ----------------------------------------------------
extern "C" void kernel_launch(void* const* d_in, const int* in_sizes, int n_in,
                              void* d_out, int out_size)
{
    (void)in_sizes; (void)n_in; (void)out_size;
    const float* table  = (const float*)d_in[0];
    const float* a_simi = (const float*)d_in[1];
    const float* t_simi = (const float*)d_in[2];
    const float* adj    = (const float*)d_in[3];
    const float* W1     = (const float*)d_in[4];
    const float* b1     = (const float*)d_in[5];
    const float* g1     = (const float*)d_in[6];
    const float* W2     = (const float*)d_in[7];
    const float* b2     = (const float*)d_in[8];
    const float* g2     = (const float*)d_in[9];
    float* out = (float*)d_out;

    static bool attr_set = false;
    if (!attr_set) {
        cudaFuncSetAttribute(gemm1_kernel,
                             cudaFuncAttributeMaxDynamicSharedMemorySize, SMEM_G);
        cudaFuncSetAttribute(gemm2_kernel,
                             cudaFuncAttributeMaxDynamicSharedMemorySize, SMEM_G);
        attr_set = true;
    }

    // weight transposes (fp32 -> fp16, coalesced). Destination chosen in-kernel.
    trans_kernel<<<dim3(N1_ / 32, K_ / 32), dim3(32, 8)>>>(W1, 0, N1_);
    trans_kernel<<<dim3(N2_ / 32, K_ / 32), dim3(32, 8)>>>(W2, 1, N2_);

    // layer 1: gather(table) [also zeroes rsum] -> GEMM1(+rsum) -> rfac
    gather_kernel<<<B_ * S_, 192>>>(table, a_simi, t_simi, adj, 0, g1);
    gemm1_kernel<<<dim3(N1_ / BN1, M_ / BM1), 256, SMEM_G>>>(b1);
    rfac_kernel<<<(M_ + 255) / 256, 256>>>();

    // layer 2: gather(norm(Yh)) -> GEMM2 with fused RMS+ReLU
    gather_kernel<<<B_ * S_, 192>>>(nullptr, a_simi, t_simi, adj, 1, g1);
    gemm2_kernel<<<M_ / BM2, 256, SMEM_G>>>(b2, g2, out);
}

// round 12
// speedup vs baseline: 2.8429x; 1.0341x over previous
#include <cuda_runtime.h>
#include <cuda_fp16.h>
#include <cstdint>

// ---------------------------------------------------------------- shapes
#define B_  8
#define S_  96
#define D_  768
#define M_  (B_ * S_ * S_)   // 73728 rows
#define K_  768
#define N1_ 768
#define N2_ 256

// GEMM tiling (mma.sync path, base ISA only)
#define BKg 32               // k per stage
#define NTg (K_ / BKg)       // 24 k-tiles
#define LDAB 80              // bytes per smem row (32 fp16 = 64B + 16B pad)
#define NSTAGE 3
// GEMM1: CTA 128x128, warp 64x32 (2M x 4N)
#define BM1 128
#define BN1 128
#define T1_A 0               // 128 rows * 80B = 10240
#define T1_W 10240
#define STG1 20480
#define SMEM_G1 (NSTAGE * STG1)    // 61440
// GEMM2: CTA 64x256, warp 32x64 (2M x 4N); full N in CTA -> fused RMS
#define BM2 64
#define BN2 256
#define T2_A 0               // 64 rows * 80B = 5120
#define T2_W 5120            // 256 rows * 80B = 20480
#define STG2 25600
#define SMEM_G2 (NSTAGE * STG2)    // 76800

// ---------------- scratch (static device globals; no allocations) ----------
// RULE: these symbols are referenced ONLY from device code, never passed as
// kernel arguments from host (host-side shadow address bug, rounds 7 & 10).
static __device__ __half g_Yh[(size_t)M_ * N1_];       // GEMM1 out (pre-norm), fp16
static __device__ float  g_rsum[M_];                   // per-row sum of squares
static __device__ float  g_rfac[M_];                   // rsqrt factors
static __device__ __half g_A[(size_t)M_ * K_];         // gather out, fp16
static __device__ __half g_W1T[(size_t)N1_ * K_];      // W^T, k-contiguous, fp16
static __device__ __half g_W2T[(size_t)N2_ * K_];

// ---------------------------------------------------------------- helpers
__device__ __forceinline__ uint32_t smem_u32(const void* p) {
    uint32_t a;
    asm("{ .reg .u64 t; cvta.to.shared.u64 t, %1; cvt.u32.u64 %0, t; }" : "=r"(a) : "l"(p));
    return a;
}

__device__ __forceinline__ void cp16(uint32_t s, const void* g) {
    asm volatile("cp.async.cg.shared.global [%0], [%1], 16;" :: "r"(s), "l"(g));
}
#define CP_COMMIT() asm volatile("cp.async.commit_group;" ::: "memory")
#define CP_WAIT1()  asm volatile("cp.async.wait_group 1;" ::: "memory")
#define CP_WAIT0()  asm volatile("cp.async.wait_group 0;" ::: "memory")

#define LDSM4(r, addr) \
    asm volatile("ldmatrix.sync.aligned.m8n8.x4.shared.b16 {%0,%1,%2,%3}, [%4];" \
        : "=r"((r)[0]), "=r"((r)[1]), "=r"((r)[2]), "=r"((r)[3]) : "r"(addr))

#define MMA_F16(Cv, Av, Bv) asm volatile( \
    "mma.sync.aligned.m16n8k16.row.col.f32.f16.f16.f32 " \
    "{%0,%1,%2,%3}, {%4,%5,%6,%7}, {%8,%9}, {%0,%1,%2,%3};\n" \
    : "+f"((Cv)[0]), "+f"((Cv)[1]), "+f"((Cv)[2]), "+f"((Cv)[3]) \
    : "r"((Av)[0]), "r"((Av)[1]), "r"((Av)[2]), "r"((Av)[3]), \
      "r"((Bv)[0]), "r"((Bv)[1]))

// ---------------- kernel 1: coalesced W -> W^T fp16 transpose ---------------
// Destination selected INSIDE device code (which=0 -> g_W1T, 1 -> g_W2T).
__global__ void trans_kernel(const float* __restrict__ W, int which, int N)
{
    __half* __restrict__ WT = which ? g_W2T : g_W1T;
    __shared__ float tile[32][33];
    const int n0 = blockIdx.x * 32, k0 = blockIdx.y * 32;
    const int tx = threadIdx.x, ty = threadIdx.y;
#pragma unroll
    for (int r = 0; r < 4; r++)
        tile[ty + 8 * r][tx] = W[(size_t)(k0 + ty + 8 * r) * N + n0 + tx];
    __syncthreads();
#pragma unroll
    for (int r = 0; r < 4; r++)
        WT[(size_t)(n0 + ty + 8 * r) * K_ + k0 + tx] = __float2half(tile[tx][ty + 8 * r]);
}

// ---------------- kernel 2: rotating-register gather stencil ----------------
__device__ __forceinline__ void fma4(float4& r, float s, const float4 v) {
    r.x += s * v.x; r.y += s * v.y; r.z += s * v.z; r.w += s * v.w;
}

__device__ __forceinline__ float4 loadrow(const float* __restrict__ hf, int src, int t,
                                          int use_norm, const float4 g4)
{
    float4 v;
    if (hf) {
        v = ((const float4*)(hf + (size_t)src * D_))[t];
    } else {
        uint2 u = *((const uint2*)(g_Yh + (size_t)src * D_) + t);
        __half2 a = *(__half2*)&u.x;
        __half2 b = *(__half2*)&u.y;
        v.x = __half2float(a.x); v.y = __half2float(a.y);
        v.z = __half2float(b.x); v.w = __half2float(b.y);
    }
    if (use_norm) {
        const float r = g_rfac[src];
        v.x = fmaxf(g4.x * v.x * r, 0.f);
        v.y = fmaxf(g4.y * v.y * r, 0.f);
        v.z = fmaxf(g4.z * v.z * r, 0.f);
        v.w = fmaxf(g4.w * v.w * r, 0.f);
    }
    return v;
}

__global__ void gather_kernel(const float* __restrict__ table,
                              const float* __restrict__ a_simi,
                              const float* __restrict__ t_simi,
                              const float* __restrict__ adj,
                              int use_norm, const float* __restrict__ gw)
{
    const int bl = blockIdx.x;            // b*S + l
    const int b = bl / S_, l = bl % S_;
    const int t = threadIdx.x;            // 0..191 (float4 over D)
    const int base = bl * S_;

    float4 g4 = make_float4(1.f, 1.f, 1.f, 1.f);
    if (use_norm) g4 = ((const float4*)gw)[t];

    const float au = (l > 0)      ? a_simi[b * S_ + l - 1] : 0.f;
    const float ad = (l < S_ - 1) ? a_simi[b * S_ + l + 1] : 0.f;

    const float4 diag = loadrow(table, base + l, t, use_norm, g4);
    float4 prev = make_float4(0.f, 0.f, 0.f, 0.f);
    float4 cur  = loadrow(table, base,     t, use_norm, g4);
    float4 nxt  = loadrow(table, base + 1, t, use_norm, g4);

    for (int k = 0; k < S_; k++) {
        const int idx = base + k;
        const float adjv = adj[idx];
        float4 r;
        r.x = 2.f * cur.x + adjv * diag.x;
        r.y = 2.f * cur.y + adjv * diag.y;
        r.z = 2.f * cur.z + adjv * diag.z;
        r.w = 2.f * cur.w + adjv * diag.w;
        if (k > 0)      fma4(r, t_simi[b * S_ + k - 1], prev);
        if (k < S_ - 1) fma4(r, t_simi[b * S_ + k + 1], nxt);
        if (l > 0)      fma4(r, au, loadrow(table, idx - S_, t, use_norm, g4));
        if (l < S_ - 1) fma4(r, ad, loadrow(table, idx + S_, t, use_norm, g4));

        __half2 v01, v23;
        v01.x = __float2half(r.x); v01.y = __float2half(r.y);
        v23.x = __float2half(r.z); v23.y = __float2half(r.w);
        __half2* pa = (__half2*)(g_A + (size_t)idx * D_) + 2 * t;
        pa[0] = v01;
        pa[1] = v23;
        if (!use_norm && t == 0) g_rsum[idx] = 0.f;

        prev = cur; cur = nxt;
        nxt = (k + 2 < S_) ? loadrow(table, idx + 2, t, use_norm, g4)
                           : make_float4(0.f, 0.f, 0.f, 0.f);
    }
}

// ---------------- kernel 3: rfac = rsqrt(rsum/D + eps) ----------------------
__global__ void rfac_kernel()
{
    int i = blockIdx.x * blockDim.x + threadIdx.x;
    if (i < M_) g_rfac[i] = rsqrtf(g_rsum[i] * (1.f / (float)N1_) + 1e-12f);
}

// ---------------- kernel 4: GEMM1  Yh = fp16(A@W1^T + b1), +rsum ------------
// CTA 128x128x32, 256 thr (8 warps 2Mx4N, warp 64x32), 3-stage cp.async,
// 2 CTAs/SM (launch_bounds 256,2).
__global__ void __launch_bounds__(256, 2)
gemm1_kernel(const float* __restrict__ bias)
{
    extern __shared__ __align__(128) char smem[];
    const int tid  = threadIdx.x;
    const int wid  = tid >> 5;
    const int lane = tid & 31;
    const int wm   = wid & 1;            // 0..1, 64 rows each
    const int wn   = wid >> 1;           // 0..3, 32 cols each
    const int m0 = blockIdx.y * BM1;
    const int n0 = blockIdx.x * BN1;
    const uint32_t sb = smem_u32(smem);

    const int lrow = tid >> 2;           // 0..63
    const int lch  = tid & 3;
    const uint32_t sRow = (uint32_t)(lrow * LDAB + lch * 16);

    // hoisted LDSM row offsets (k-invariant)
    uint32_t aOff[4], wOff[2];
#pragma unroll
    for (int mi = 0; mi < 4; mi++)
        aOff[mi] = (uint32_t)((wm * 64 + mi * 16 + (lane & 15)) * LDAB) + T1_A;
#pragma unroll
    for (int nj = 0; nj < 2; nj++)
        wOff[nj] = (uint32_t)((wn * 32 + nj * 16 + (lane & 15)) * LDAB) + T1_W;

    float c[4][4][4] = {};

#define LOAD_STAGE1(st, kt_) do {                                              \
        uint32_t s = sb + (uint32_t)(st) * STG1 + sRow;                        \
        _Pragma("unroll")                                                      \
        for (int i_ = 0; i_ < 2; i_++) {                                       \
            size_t gA_ = (size_t)(m0 + lrow + i_ * 64) * K_ + (kt_) + lch * 8; \
            cp16(s + T1_A + (uint32_t)(i_ * 64 * LDAB), g_A + gA_);            \
            size_t gW_ = (size_t)(n0 + lrow + i_ * 64) * K_ + (kt_) + lch * 8; \
            cp16(s + T1_W + (uint32_t)(i_ * 64 * LDAB), g_W1T + gW_);          \
        }                                                                      \
        CP_COMMIT();                                                           \
    } while (0)

    LOAD_STAGE1(0, 0);
    LOAD_STAGE1(1, BKg);

    for (int t = 0; t < NTg; t++) {
        if (t < NTg - 1) CP_WAIT1(); else CP_WAIT0();
        __syncthreads();
        if (t + 2 < NTg) LOAD_STAGE1((t + 2) % NSTAGE, (t + 2) * BKg);

        const uint32_t bufb = sb + (uint32_t)(t % NSTAGE) * STG1;
#pragma unroll
        for (int ks = 0; ks < 2; ks++) {
            const uint32_t kb = bufb + (uint32_t)(ks * 32 + (lane >> 4) * 16);
            uint32_t aw[4][4], bw[2][4];
#pragma unroll
            for (int mi = 0; mi < 4; mi++) LDSM4(aw[mi], kb + aOff[mi]);
#pragma unroll
            for (int nj = 0; nj < 2; nj++) LDSM4(bw[nj], kb + wOff[nj]);
#pragma unroll
            for (int mi = 0; mi < 4; mi++)
#pragma unroll
                for (int nj = 0; nj < 2; nj++) {
                    uint32_t f0[2] = {bw[nj][0], bw[nj][2]};
                    uint32_t f1[2] = {bw[nj][1], bw[nj][3]};
                    MMA_F16(c[mi][2 * nj],     aw[mi], f0);
                    MMA_F16(c[mi][2 * nj + 1], aw[mi], f1);
                }
        }
        __syncthreads();
    }
#undef LOAD_STAGE1

    // epilogue: + bias, fp16 store, per-row sumsq via atomics
#pragma unroll
    for (int mi = 0; mi < 4; mi++) {
        const int row = m0 + wm * 64 + mi * 16 + (lane >> 2);
        float p0 = 0.f, p1 = 0.f;
#pragma unroll
        for (int ni = 0; ni < 4; ni++) {
            const int col = n0 + wn * 32 + ni * 8 + 2 * (lane & 3);
            float2 bv = *(const float2*)(bias + col);
            float2 v0 = make_float2(c[mi][ni][0] + bv.x, c[mi][ni][1] + bv.y);
            float2 v1 = make_float2(c[mi][ni][2] + bv.x, c[mi][ni][3] + bv.y);
            *(__half2*)(g_Yh + (size_t)row * N1_ + col)       = __floats2half2_rn(v0.x, v0.y);
            *(__half2*)(g_Yh + (size_t)(row + 8) * N1_ + col) = __floats2half2_rn(v1.x, v1.y);
            p0 += v0.x * v0.x + v0.y * v0.y;
            p1 += v1.x * v1.x + v1.y * v1.y;
        }
        p0 += __shfl_xor_sync(0xffffffffu, p0, 1);
        p0 += __shfl_xor_sync(0xffffffffu, p0, 2);
        p1 += __shfl_xor_sync(0xffffffffu, p1, 1);
        p1 += __shfl_xor_sync(0xffffffffu, p1, 2);
        if ((lane & 3) == 0) {
            atomicAdd(&g_rsum[row], p0);
            atomicAdd(&g_rsum[row + 8], p1);
        }
    }
}

// ---------------- kernel 5: GEMM2 + fused T5 RMS-norm + ReLU ----------------
// CTA 64x256x32 (full N2 in CTA), 256 thr (8 warps 2Mx4N, warp 32x64),
// 2 CTAs/SM.
__global__ void __launch_bounds__(256, 2)
gemm2_kernel(const float* __restrict__ bias, const float* __restrict__ gw,
             float* __restrict__ out)
{
    extern __shared__ __align__(128) char smem[];
    const int tid  = threadIdx.x;
    const int wid  = tid >> 5;
    const int lane = tid & 31;
    const int wm   = wid & 1;            // 0..1, 32 rows each
    const int wn   = wid >> 1;           // 0..3, 64 cols each
    const int m0 = blockIdx.x * BM2;
    const uint32_t sb = smem_u32(smem);

    const int lrow = tid >> 2;           // 0..63
    const int lch  = tid & 3;
    const uint32_t sRow = (uint32_t)(lrow * LDAB + lch * 16);

    uint32_t aOff[2], wOff[4];
#pragma unroll
    for (int mi = 0; mi < 2; mi++)
        aOff[mi] = (uint32_t)((wm * 32 + mi * 16 + (lane & 15)) * LDAB) + T2_A;
#pragma unroll
    for (int nj = 0; nj < 4; nj++)
        wOff[nj] = (uint32_t)((wn * 64 + nj * 16 + (lane & 15)) * LDAB) + T2_W;

    float c[2][8][4] = {};

#define LOAD_STAGE2(st, kt_) do {                                              \
        uint32_t s = sb + (uint32_t)(st) * STG2 + sRow;                        \
        {                                                                      \
            size_t gA_ = (size_t)(m0 + lrow) * K_ + (kt_) + lch * 8;           \
            cp16(s + T2_A, g_A + gA_);                                         \
        }                                                                      \
        _Pragma("unroll")                                                      \
        for (int i_ = 0; i_ < 4; i_++) {                                       \
            size_t gW_ = (size_t)(lrow + i_ * 64) * K_ + (kt_) + lch * 8;      \
            cp16(s + T2_W + (uint32_t)(i_ * 64 * LDAB), g_W2T + gW_);          \
        }                                                                      \
        CP_COMMIT();                                                           \
    } while (0)

    LOAD_STAGE2(0, 0);
    LOAD_STAGE2(1, BKg);

    for (int t = 0; t < NTg; t++) {
        if (t < NTg - 1) CP_WAIT1(); else CP_WAIT0();
        __syncthreads();
        if (t + 2 < NTg) LOAD_STAGE2((t + 2) % NSTAGE, (t + 2) * BKg);

        const uint32_t bufb = sb + (uint32_t)(t % NSTAGE) * STG2;
#pragma unroll
        for (int ks = 0; ks < 2; ks++) {
            const uint32_t kb = bufb + (uint32_t)(ks * 32 + (lane >> 4) * 16);
            uint32_t aw[2][4], bw[4][4];
#pragma unroll
            for (int mi = 0; mi < 2; mi++) LDSM4(aw[mi], kb + aOff[mi]);
#pragma unroll
            for (int nj = 0; nj < 4; nj++) LDSM4(bw[nj], kb + wOff[nj]);
#pragma unroll
            for (int mi = 0; mi < 2; mi++)
#pragma unroll
                for (int nj = 0; nj < 4; nj++) {
                    uint32_t f0[2] = {bw[nj][0], bw[nj][2]};
                    uint32_t f1[2] = {bw[nj][1], bw[nj][3]};
                    MMA_F16(c[mi][2 * nj],     aw[mi], f0);
                    MMA_F16(c[mi][2 * nj + 1], aw[mi], f1);
                }
        }
        __syncthreads();
    }
#undef LOAD_STAGE2

    // ---- fused epilogue: row sumsq (cross-warp via smem), then norm+relu ----
    float* sp = (float*)smem;              // 64 rows x 4 wn partials
#pragma unroll
    for (int mi = 0; mi < 2; mi++) {
        const int prow = wm * 32 + mi * 16 + (lane >> 2);
        float p0 = 0.f, p1 = 0.f;
#pragma unroll
        for (int ni = 0; ni < 8; ni++) {
            const int col = wn * 64 + ni * 8 + 2 * (lane & 3);
            float2 bv = *(const float2*)(bias + col);
            float2 v0 = make_float2(c[mi][ni][0] + bv.x, c[mi][ni][1] + bv.y);
            float2 v1 = make_float2(c[mi][ni][2] + bv.x, c[mi][ni][3] + bv.y);
            p0 += v0.x * v0.x + v0.y * v0.y;
            p1 += v1.x * v1.x + v1.y * v1.y;
        }
        p0 += __shfl_xor_sync(0xffffffffu, p0, 1);
        p0 += __shfl_xor_sync(0xffffffffu, p0, 2);
        p1 += __shfl_xor_sync(0xffffffffu, p1, 1);
        p1 += __shfl_xor_sync(0xffffffffu, p1, 2);
        if ((lane & 3) == 0) {
            sp[prow * 4 + wn]       = p0;
            sp[(prow + 8) * 4 + wn] = p1;
        }
    }
    __syncthreads();
#pragma unroll
    for (int mi = 0; mi < 2; mi++) {
        const int prow = wm * 32 + mi * 16 + (lane >> 2);
        const float tot0 = sp[prow * 4] + sp[prow * 4 + 1] + sp[prow * 4 + 2] + sp[prow * 4 + 3];
        const float tot1 = sp[(prow + 8) * 4] + sp[(prow + 8) * 4 + 1] +
                           sp[(prow + 8) * 4 + 2] + sp[(prow + 8) * 4 + 3];
        const float r0 = rsqrtf(tot0 * (1.f / (float)N2_) + 1e-12f);
        const float r1 = rsqrtf(tot1 * (1.f / (float)N2_) + 1e-12f);
        const size_t row = (size_t)(m0 + prow);
#pragma unroll
        for (int ni = 0; ni < 8; ni++) {
            const int col = wn * 64 + ni * 8 + 2 * (lane & 3);
            float2 bv = *(const float2*)(bias + col);
            float2 gv = *(const float2*)(gw + col);
            float2 o0, o1;
            o0.x = fmaxf(gv.x * (c[mi][ni][0] + bv.x) * r0, 0.f);
            o0.y = fmaxf(gv.y * (c[mi][ni][1] + bv.y) * r0, 0.f);
            o1.x = fmaxf(gv.x * (c[mi][ni][2] + bv.x) * r1, 0.f);
            o1.y = fmaxf(gv.y * (c[mi][ni][3] + bv.y) * r1, 0.f);
            *(float2*)(out + row * N2_ + col)       = o0;
            *(float2*)(out + (row + 8) * N2_ + col) = o1;
        }
    }
}

// ---------------- launch ----------------------------------------------------
extern "C" void kernel_launch(void* const* d_in, const int* in_sizes, int n_in,
                              void* d_out, int out_size)
{
    (void)in_sizes; (void)n_in; (void)out_size;
    const float* table  = (const float*)d_in[0];
    const float* a_simi = (const float*)d_in[1];
    const float* t_simi = (const float*)d_in[2];
    const float* adj    = (const float*)d_in[3];
    const float* W1     = (const float*)d_in[4];
    const float* b1     = (const float*)d_in[5];
    const float* g1     = (const float*)d_in[6];
    const float* W2     = (const float*)d_in[7];
    const float* b2     = (const float*)d_in[8];
    const float* g2     = (const float*)d_in[9];
    float* out = (float*)d_out;

    static bool attr_set = false;
    if (!attr_set) {
        cudaFuncSetAttribute(gemm1_kernel,
                             cudaFuncAttributeMaxDynamicSharedMemorySize, SMEM_G1);
        cudaFuncSetAttribute(gemm2_kernel,
                             cudaFuncAttributeMaxDynamicSharedMemorySize, SMEM_G2);
        attr_set = true;
    }

    // weight transposes (fp32 -> fp16, coalesced). Destination chosen in-kernel.
    trans_kernel<<<dim3(N1_ / 32, K_ / 32), dim3(32, 8)>>>(W1, 0, N1_);
    trans_kernel<<<dim3(N2_ / 32, K_ / 32), dim3(32, 8)>>>(W2, 1, N2_);

    // layer 1: gather(table) [also zeroes rsum] -> GEMM1(+rsum) -> rfac
    gather_kernel<<<B_ * S_, 192>>>(table, a_simi, t_simi, adj, 0, g1);
    gemm1_kernel<<<dim3(N1_ / BN1, M_ / BM1), 256, SMEM_G1>>>(b1);
    rfac_kernel<<<(M_ + 255) / 256, 256>>>();

    // layer 2: gather(norm(Yh)) -> GEMM2 with fused RMS+ReLU
    gather_kernel<<<B_ * S_, 192>>>(nullptr, a_simi, t_simi, adj, 1, g1);
    gemm2_kernel<<<M_ / BM2, 256, SMEM_G2>>>(b2, g2, out);
}

// round 13
// speedup vs baseline: 2.8516x; 1.0031x over previous
#include <cuda_runtime.h>
#include <cuda_fp16.h>
#include <cstdint>

// ---------------------------------------------------------------- shapes
#define B_  8
#define S_  96
#define D_  768
#define M_  (B_ * S_ * S_)   // 73728 rows
#define K_  768
#define N1_ 768
#define N2_ 256

// GEMM tiling (mma.sync path, base ISA only)
#define BKg 32               // k per stage
#define NTg (K_ / BKg)       // 24 k-tiles
#define LDAB 80              // bytes per smem row (32 fp16 = 64B + 16B pad)
#define NSTAGE 4
// GEMM1: CTA 128x128, warp 64x32 (2M x 4N)
#define BM1 128
#define BN1 128
#define T1_A 0               // 128 rows * 80B = 10240
#define T1_W 10240
#define STG1 20480
#define SMEM_G1 (NSTAGE * STG1)    // 81920
// GEMM2: CTA 64x256, warp 32x64 (2M x 4N); full N in CTA -> fused RMS
#define BM2 64
#define BN2 256
#define T2_A 0               // 64 rows * 80B = 5120
#define T2_W 5120            // 256 rows * 80B = 20480
#define STG2 25600
#define SMEM_G2 (NSTAGE * STG2)    // 102400

// ---------------- scratch (static device globals; no allocations) ----------
// RULE: these symbols are referenced ONLY from device code, never passed as
// kernel arguments from host (host-side shadow address bug, rounds 7 & 10).
static __device__ __half g_Yh[(size_t)M_ * N1_];       // GEMM1 out (pre-norm), fp16
static __device__ float  g_rsum[M_];                   // per-row sum of squares
static __device__ float  g_rfac[M_];                   // rsqrt factors
static __device__ __half g_A[(size_t)M_ * K_];         // gather out, fp16
static __device__ __half g_W1T[(size_t)N1_ * K_];      // W^T, k-contiguous, fp16
static __device__ __half g_W2T[(size_t)N2_ * K_];

// ---------------------------------------------------------------- helpers
__device__ __forceinline__ uint32_t smem_u32(const void* p) {
    uint32_t a;
    asm("{ .reg .u64 t; cvta.to.shared.u64 t, %1; cvt.u32.u64 %0, t; }" : "=r"(a) : "l"(p));
    return a;
}

__device__ __forceinline__ void cp16(uint32_t s, const void* g) {
    asm volatile("cp.async.cg.shared.global [%0], [%1], 16;" :: "r"(s), "l"(g));
}
#define CP_COMMIT() asm volatile("cp.async.commit_group;" ::: "memory")
#define CP_WAIT2()  asm volatile("cp.async.wait_group 2;" ::: "memory")
#define CP_WAIT1()  asm volatile("cp.async.wait_group 1;" ::: "memory")
#define CP_WAIT0()  asm volatile("cp.async.wait_group 0;" ::: "memory")

#define LDSM4(r, addr) \
    asm volatile("ldmatrix.sync.aligned.m8n8.x4.shared.b16 {%0,%1,%2,%3}, [%4];" \
        : "=r"((r)[0]), "=r"((r)[1]), "=r"((r)[2]), "=r"((r)[3]) : "r"(addr))

#define MMA_F16(Cv, Av, Bv) asm volatile( \
    "mma.sync.aligned.m16n8k16.row.col.f32.f16.f16.f32 " \
    "{%0,%1,%2,%3}, {%4,%5,%6,%7}, {%8,%9}, {%0,%1,%2,%3};\n" \
    : "+f"((Cv)[0]), "+f"((Cv)[1]), "+f"((Cv)[2]), "+f"((Cv)[3]) \
    : "r"((Av)[0]), "r"((Av)[1]), "r"((Av)[2]), "r"((Av)[3]), \
      "r"((Bv)[0]), "r"((Bv)[1]))

// ---------------- kernel 1: coalesced W -> W^T fp16 transpose ---------------
// Destination selected INSIDE device code (which=0 -> g_W1T, 1 -> g_W2T).
__global__ void trans_kernel(const float* __restrict__ W, int which, int N)
{
    __half* __restrict__ WT = which ? g_W2T : g_W1T;
    __shared__ float tile[32][33];
    const int n0 = blockIdx.x * 32, k0 = blockIdx.y * 32;
    const int tx = threadIdx.x, ty = threadIdx.y;
#pragma unroll
    for (int r = 0; r < 4; r++)
        tile[ty + 8 * r][tx] = W[(size_t)(k0 + ty + 8 * r) * N + n0 + tx];
    __syncthreads();
#pragma unroll
    for (int r = 0; r < 4; r++)
        WT[(size_t)(n0 + ty + 8 * r) * K_ + k0 + tx] = __float2half(tile[tx][ty + 8 * r]);
}

// ---------------- kernel 2: rotating-register gather stencil ----------------
// Grid = B*S*2: each block handles half the k-range of one (b,l) slab.
__device__ __forceinline__ void fma4(float4& r, float s, const float4 v) {
    r.x += s * v.x; r.y += s * v.y; r.z += s * v.z; r.w += s * v.w;
}

__device__ __forceinline__ float4 loadrow(const float* __restrict__ hf, int src, int t,
                                          int use_norm, const float4 g4)
{
    float4 v;
    if (hf) {
        v = ((const float4*)(hf + (size_t)src * D_))[t];
    } else {
        uint2 u = *((const uint2*)(g_Yh + (size_t)src * D_) + t);
        __half2 a = *(__half2*)&u.x;
        __half2 b = *(__half2*)&u.y;
        v.x = __half2float(a.x); v.y = __half2float(a.y);
        v.z = __half2float(b.x); v.w = __half2float(b.y);
    }
    if (use_norm) {
        const float r = g_rfac[src];
        v.x = fmaxf(g4.x * v.x * r, 0.f);
        v.y = fmaxf(g4.y * v.y * r, 0.f);
        v.z = fmaxf(g4.z * v.z * r, 0.f);
        v.w = fmaxf(g4.w * v.w * r, 0.f);
    }
    return v;
}

__global__ void gather_kernel(const float* __restrict__ table,
                              const float* __restrict__ a_simi,
                              const float* __restrict__ t_simi,
                              const float* __restrict__ adj,
                              int use_norm, const float* __restrict__ gw)
{
    const int bl = blockIdx.x >> 1;       // b*S + l
    const int half = blockIdx.x & 1;
    const int b = bl / S_, l = bl % S_;
    const int t = threadIdx.x;            // 0..191 (float4 over D)
    const int base = bl * S_;
    const int k0 = half * (S_ / 2);
    const int k1 = k0 + (S_ / 2);

    float4 g4 = make_float4(1.f, 1.f, 1.f, 1.f);
    if (use_norm) g4 = ((const float4*)gw)[t];

    const float au = (l > 0)      ? a_simi[b * S_ + l - 1] : 0.f;
    const float ad = (l < S_ - 1) ? a_simi[b * S_ + l + 1] : 0.f;

    const float4 diag = loadrow(table, base + l, t, use_norm, g4);
    float4 prev = (k0 > 0) ? loadrow(table, base + k0 - 1, t, use_norm, g4)
                           : make_float4(0.f, 0.f, 0.f, 0.f);
    float4 cur  = loadrow(table, base + k0, t, use_norm, g4);
    float4 nxt  = loadrow(table, base + k0 + 1, t, use_norm, g4);

    for (int k = k0; k < k1; k++) {
        const int idx = base + k;
        const float adjv = adj[idx];
        float4 r;
        r.x = 2.f * cur.x + adjv * diag.x;
        r.y = 2.f * cur.y + adjv * diag.y;
        r.z = 2.f * cur.z + adjv * diag.z;
        r.w = 2.f * cur.w + adjv * diag.w;
        if (k > 0)      fma4(r, t_simi[b * S_ + k - 1], prev);
        if (k < S_ - 1) fma4(r, t_simi[b * S_ + k + 1], nxt);
        if (l > 0)      fma4(r, au, loadrow(table, idx - S_, t, use_norm, g4));
        if (l < S_ - 1) fma4(r, ad, loadrow(table, idx + S_, t, use_norm, g4));

        __half2 v01, v23;
        v01.x = __float2half(r.x); v01.y = __float2half(r.y);
        v23.x = __float2half(r.z); v23.y = __float2half(r.w);
        __half2* pa = (__half2*)(g_A + (size_t)idx * D_) + 2 * t;
        pa[0] = v01;
        pa[1] = v23;
        if (!use_norm && t == 0) g_rsum[idx] = 0.f;

        prev = cur; cur = nxt;
        nxt = (k + 2 < S_) ? loadrow(table, idx + 2, t, use_norm, g4)
                           : make_float4(0.f, 0.f, 0.f, 0.f);
    }
}

// ---------------- kernel 3: rfac = rsqrt(rsum/D + eps) ----------------------
__global__ void rfac_kernel()
{
    int i = blockIdx.x * blockDim.x + threadIdx.x;
    if (i < M_) g_rfac[i] = rsqrtf(g_rsum[i] * (1.f / (float)N1_) + 1e-12f);
}

// ---------------- kernel 4: GEMM1  Yh = fp16(A@W1^T + b1), +rsum ------------
// CTA 128x128x32, 256 thr (8 warps 2Mx4N, warp 64x32), 4-stage cp.async,
// SINGLE barrier per k-tile, 2 CTAs/SM.
__global__ void __launch_bounds__(256, 2)
gemm1_kernel(const float* __restrict__ bias)
{
    extern __shared__ __align__(128) char smem[];
    const int tid  = threadIdx.x;
    const int wid  = tid >> 5;
    const int lane = tid & 31;
    const int wm   = wid & 1;            // 0..1, 64 rows each
    const int wn   = wid >> 1;           // 0..3, 32 cols each
    const int m0 = blockIdx.y * BM1;
    const int n0 = blockIdx.x * BN1;
    const uint32_t sb = smem_u32(smem);

    const int lrow = tid >> 2;           // 0..63
    const int lch  = tid & 3;
    const uint32_t sRow = (uint32_t)(lrow * LDAB + lch * 16);

    // hoisted LDSM row offsets (k-invariant)
    uint32_t aOff[4], wOff[2];
#pragma unroll
    for (int mi = 0; mi < 4; mi++)
        aOff[mi] = (uint32_t)((wm * 64 + mi * 16 + (lane & 15)) * LDAB) + T1_A;
#pragma unroll
    for (int nj = 0; nj < 2; nj++)
        wOff[nj] = (uint32_t)((wn * 32 + nj * 16 + (lane & 15)) * LDAB) + T1_W;

    float c[4][4][4] = {};

#define LOAD_STAGE1(st, kt_) do {                                              \
        uint32_t s = sb + (uint32_t)(st) * STG1 + sRow;                        \
        _Pragma("unroll")                                                      \
        for (int i_ = 0; i_ < 2; i_++) {                                       \
            size_t gA_ = (size_t)(m0 + lrow + i_ * 64) * K_ + (kt_) + lch * 8; \
            cp16(s + T1_A + (uint32_t)(i_ * 64 * LDAB), g_A + gA_);            \
            size_t gW_ = (size_t)(n0 + lrow + i_ * 64) * K_ + (kt_) + lch * 8; \
            cp16(s + T1_W + (uint32_t)(i_ * 64 * LDAB), g_W1T + gW_);          \
        }                                                                      \
        CP_COMMIT();                                                           \
    } while (0)

    LOAD_STAGE1(0, 0);
    LOAD_STAGE1(1, BKg);
    LOAD_STAGE1(2, 2 * BKg);

    for (int t = 0; t < NTg; t++) {
        if (t < NTg - 2)      CP_WAIT2();
        else if (t == NTg - 2) CP_WAIT1();
        else                   CP_WAIT0();
        __syncthreads();      // all warps see stage t filled; also licenses the
                              // overwrite of stage (t+3)%4 (compute of t-1 done)
        if (t + 3 < NTg) LOAD_STAGE1((t + 3) % NSTAGE, (t + 3) * BKg);

        const uint32_t bufb = sb + (uint32_t)(t % NSTAGE) * STG1;
#pragma unroll
        for (int ks = 0; ks < 2; ks++) {
            const uint32_t kb = bufb + (uint32_t)(ks * 32 + (lane >> 4) * 16);
            uint32_t aw[4][4], bw[2][4];
#pragma unroll
            for (int mi = 0; mi < 4; mi++) LDSM4(aw[mi], kb + aOff[mi]);
#pragma unroll
            for (int nj = 0; nj < 2; nj++) LDSM4(bw[nj], kb + wOff[nj]);
#pragma unroll
            for (int mi = 0; mi < 4; mi++)
#pragma unroll
                for (int nj = 0; nj < 2; nj++) {
                    uint32_t f0[2] = {bw[nj][0], bw[nj][2]};
                    uint32_t f1[2] = {bw[nj][1], bw[nj][3]};
                    MMA_F16(c[mi][2 * nj],     aw[mi], f0);
                    MMA_F16(c[mi][2 * nj + 1], aw[mi], f1);
                }
        }
        // no trailing barrier: next overwrite of this stage happens only after
        // the barrier of iteration t+1, which implies all compute of t is done
    }
#undef LOAD_STAGE1

    // epilogue: + bias, fp16 store, per-row sumsq via atomics
#pragma unroll
    for (int mi = 0; mi < 4; mi++) {
        const int row = m0 + wm * 64 + mi * 16 + (lane >> 2);
        float p0 = 0.f, p1 = 0.f;
#pragma unroll
        for (int ni = 0; ni < 4; ni++) {
            const int col = n0 + wn * 32 + ni * 8 + 2 * (lane & 3);
            float2 bv = *(const float2*)(bias + col);
            float2 v0 = make_float2(c[mi][ni][0] + bv.x, c[mi][ni][1] + bv.y);
            float2 v1 = make_float2(c[mi][ni][2] + bv.x, c[mi][ni][3] + bv.y);
            *(__half2*)(g_Yh + (size_t)row * N1_ + col)       = __floats2half2_rn(v0.x, v0.y);
            *(__half2*)(g_Yh + (size_t)(row + 8) * N1_ + col) = __floats2half2_rn(v1.x, v1.y);
            p0 += v0.x * v0.x + v0.y * v0.y;
            p1 += v1.x * v1.x + v1.y * v1.y;
        }
        p0 += __shfl_xor_sync(0xffffffffu, p0, 1);
        p0 += __shfl_xor_sync(0xffffffffu, p0, 2);
        p1 += __shfl_xor_sync(0xffffffffu, p1, 1);
        p1 += __shfl_xor_sync(0xffffffffu, p1, 2);
        if ((lane & 3) == 0) {
            atomicAdd(&g_rsum[row], p0);
            atomicAdd(&g_rsum[row + 8], p1);
        }
    }
}

// ---------------- kernel 5: GEMM2 + fused T5 RMS-norm + ReLU ----------------
// CTA 64x256x32 (full N2 in CTA), 256 thr (8 warps 2Mx4N, warp 32x64),
// 4-stage cp.async, single barrier per k-tile, 2 CTAs/SM.
__global__ void __launch_bounds__(256, 2)
gemm2_kernel(const float* __restrict__ bias, const float* __restrict__ gw,
             float* __restrict__ out)
{
    extern __shared__ __align__(128) char smem[];
    const int tid  = threadIdx.x;
    const int wid  = tid >> 5;
    const int lane = tid & 31;
    const int wm   = wid & 1;            // 0..1, 32 rows each
    const int wn   = wid >> 1;           // 0..3, 64 cols each
    const int m0 = blockIdx.x * BM2;
    const uint32_t sb = smem_u32(smem);

    const int lrow = tid >> 2;           // 0..63
    const int lch  = tid & 3;
    const uint32_t sRow = (uint32_t)(lrow * LDAB + lch * 16);

    uint32_t aOff[2], wOff[4];
#pragma unroll
    for (int mi = 0; mi < 2; mi++)
        aOff[mi] = (uint32_t)((wm * 32 + mi * 16 + (lane & 15)) * LDAB) + T2_A;
#pragma unroll
    for (int nj = 0; nj < 4; nj++)
        wOff[nj] = (uint32_t)((wn * 64 + nj * 16 + (lane & 15)) * LDAB) + T2_W;

    float c[2][8][4] = {};

#define LOAD_STAGE2(st, kt_) do {                                              \
        uint32_t s = sb + (uint32_t)(st) * STG2 + sRow;                        \
        {                                                                      \
            size_t gA_ = (size_t)(m0 + lrow) * K_ + (kt_) + lch * 8;           \
            cp16(s + T2_A, g_A + gA_);                                         \
        }                                                                      \
        _Pragma("unroll")                                                      \
        for (int i_ = 0; i_ < 4; i_++) {                                       \
            size_t gW_ = (size_t)(lrow + i_ * 64) * K_ + (kt_) + lch * 8;      \
            cp16(s + T2_W + (uint32_t)(i_ * 64 * LDAB), g_W2T + gW_);          \
        }                                                                      \
        CP_COMMIT();                                                           \
    } while (0)

    LOAD_STAGE2(0, 0);
    LOAD_STAGE2(1, BKg);
    LOAD_STAGE2(2, 2 * BKg);

    for (int t = 0; t < NTg; t++) {
        if (t < NTg - 2)      CP_WAIT2();
        else if (t == NTg - 2) CP_WAIT1();
        else                   CP_WAIT0();
        __syncthreads();
        if (t + 3 < NTg) LOAD_STAGE2((t + 3) % NSTAGE, (t + 3) * BKg);

        const uint32_t bufb = sb + (uint32_t)(t % NSTAGE) * STG2;
#pragma unroll
        for (int ks = 0; ks < 2; ks++) {
            const uint32_t kb = bufb + (uint32_t)(ks * 32 + (lane >> 4) * 16);
            uint32_t aw[2][4], bw[4][4];
#pragma unroll
            for (int mi = 0; mi < 2; mi++) LDSM4(aw[mi], kb + aOff[mi]);
#pragma unroll
            for (int nj = 0; nj < 4; nj++) LDSM4(bw[nj], kb + wOff[nj]);
#pragma unroll
            for (int mi = 0; mi < 2; mi++)
#pragma unroll
                for (int nj = 0; nj < 4; nj++) {
                    uint32_t f0[2] = {bw[nj][0], bw[nj][2]};
                    uint32_t f1[2] = {bw[nj][1], bw[nj][3]};
                    MMA_F16(c[mi][2 * nj],     aw[mi], f0);
                    MMA_F16(c[mi][2 * nj + 1], aw[mi], f1);
                }
        }
    }
#undef LOAD_STAGE2

    // ---- fused epilogue: row sumsq (cross-warp via smem), then norm+relu ----
    __syncthreads();                       // all compute done before smem reuse
    float* sp = (float*)smem;              // 64 rows x 4 wn partials
#pragma unroll
    for (int mi = 0; mi < 2; mi++) {
        const int prow = wm * 32 + mi * 16 + (lane >> 2);
        float p0 = 0.f, p1 = 0.f;
#pragma unroll
        for (int ni = 0; ni < 8; ni++) {
            const int col = wn * 64 + ni * 8 + 2 * (lane & 3);
            float2 bv = *(const float2*)(bias + col);
            float2 v0 = make_float2(c[mi][ni][0] + bv.x, c[mi][ni][1] + bv.y);
            float2 v1 = make_float2(c[mi][ni][2] + bv.x, c[mi][ni][3] + bv.y);
            p0 += v0.x * v0.x + v0.y * v0.y;
            p1 += v1.x * v1.x + v1.y * v1.y;
        }
        p0 += __shfl_xor_sync(0xffffffffu, p0, 1);
        p0 += __shfl_xor_sync(0xffffffffu, p0, 2);
        p1 += __shfl_xor_sync(0xffffffffu, p1, 1);
        p1 += __shfl_xor_sync(0xffffffffu, p1, 2);
        if ((lane & 3) == 0) {
            sp[prow * 4 + wn]       = p0;
            sp[(prow + 8) * 4 + wn] = p1;
        }
    }
    __syncthreads();
#pragma unroll
    for (int mi = 0; mi < 2; mi++) {
        const int prow = wm * 32 + mi * 16 + (lane >> 2);
        const float tot0 = sp[prow * 4] + sp[prow * 4 + 1] + sp[prow * 4 + 2] + sp[prow * 4 + 3];
        const float tot1 = sp[(prow + 8) * 4] + sp[(prow + 8) * 4 + 1] +
                           sp[(prow + 8) * 4 + 2] + sp[(prow + 8) * 4 + 3];
        const float r0 = rsqrtf(tot0 * (1.f / (float)N2_) + 1e-12f);
        const float r1 = rsqrtf(tot1 * (1.f / (float)N2_) + 1e-12f);
        const size_t row = (size_t)(m0 + prow);
#pragma unroll
        for (int ni = 0; ni < 8; ni++) {
            const int col = wn * 64 + ni * 8 + 2 * (lane & 3);
            float2 bv = *(const float2*)(bias + col);
            float2 gv = *(const float2*)(gw + col);
            float2 o0, o1;
            o0.x = fmaxf(gv.x * (c[mi][ni][0] + bv.x) * r0, 0.f);
            o0.y = fmaxf(gv.y * (c[mi][ni][1] + bv.y) * r0, 0.f);
            o1.x = fmaxf(gv.x * (c[mi][ni][2] + bv.x) * r1, 0.f);
            o1.y = fmaxf(gv.y * (c[mi][ni][3] + bv.y) * r1, 0.f);
            *(float2*)(out + row * N2_ + col)       = o0;
            *(float2*)(out + (row + 8) * N2_ + col) = o1;
        }
    }
}

// ---------------- launch ----------------------------------------------------
extern "C" void kernel_launch(void* const* d_in, const int* in_sizes, int n_in,
                              void* d_out, int out_size)
{
    (void)in_sizes; (void)n_in; (void)out_size;
    const float* table  = (const float*)d_in[0];
    const float* a_simi = (const float*)d_in[1];
    const float* t_simi = (const float*)d_in[2];
    const float* adj    = (const float*)d_in[3];
    const float* W1     = (const float*)d_in[4];
    const float* b1     = (const float*)d_in[5];
    const float* g1     = (const float*)d_in[6];
    const float* W2     = (const float*)d_in[7];
    const float* b2     = (const float*)d_in[8];
    const float* g2     = (const float*)d_in[9];
    float* out = (float*)d_out;

    static bool attr_set = false;
    if (!attr_set) {
        cudaFuncSetAttribute(gemm1_kernel,
                             cudaFuncAttributeMaxDynamicSharedMemorySize, SMEM_G1);
        cudaFuncSetAttribute(gemm2_kernel,
                             cudaFuncAttributeMaxDynamicSharedMemorySize, SMEM_G2);
        attr_set = true;
    }

    // weight transposes (fp32 -> fp16, coalesced). Destination chosen in-kernel.
    trans_kernel<<<dim3(N1_ / 32, K_ / 32), dim3(32, 8)>>>(W1, 0, N1_);
    trans_kernel<<<dim3(N2_ / 32, K_ / 32), dim3(32, 8)>>>(W2, 1, N2_);

    // layer 1: gather(table) [also zeroes rsum] -> GEMM1(+rsum) -> rfac
    gather_kernel<<<B_ * S_ * 2, 192>>>(table, a_simi, t_simi, adj, 0, g1);
    gemm1_kernel<<<dim3(N1_ / BN1, M_ / BM1), 256, SMEM_G1>>>(b1);
    rfac_kernel<<<(M_ + 255) / 256, 256>>>();

    // layer 2: gather(norm(Yh)) -> GEMM2 with fused RMS+ReLU
    gather_kernel<<<B_ * S_ * 2, 192>>>(nullptr, a_simi, t_simi, adj, 1, g1);
    gemm2_kernel<<<M_ / BM2, 256, SMEM_G2>>>(b2, g2, out);
}